// round 1
// baseline (speedup 1.0000x reference)
#include <cuda_runtime.h>
#include <math.h>

#define Bq 2
#define Lq 1024
#define Dq 1024
#define Hq 16
#define DKq 64
#define CHUNK 128
#define NC (Lq/CHUNK)   /* 8 */

// ---------------- scratch (device globals; no allocation allowed) ----------------
__device__ float g_qkv [Bq*Lq*3*Dq];       // [b,l, {q|k|v} blocks of 1024]
__device__ float g_kn  [Bq*Lq*Dq];         // layernormed k, [b,l,h,dk]
__device__ float g_so  [Bq*Lq*Dq];         // softmax attention out, [b,l,h,dk]
__device__ float g_ymix[Bq*Lq*Dq];         // gated mix, [b,l,d]
__device__ float g_ret [Hq*DKq*DKq];
__device__ float g_coef[Hq*DKq*DKq];
__device__ float g_retC[Hq*DKq*DKq];       // retention^CHUNK
__device__ float g_A   [Bq*Hq*NC*DKq*DKq]; // chunk-local suffix sums
__device__ float g_Fin [Bq*Hq*NC*DKq*DKq]; // F at chunk starts

// ---------------- generic fp32 GEMM: C[M,N] = A[M,K] @ B[K,N] ----------------
// 128x128x16 tiles, 256 threads, 8x8 micro-tile per thread.
__global__ __launch_bounds__(256) void gemm128(const float* __restrict__ A,
                                               const float* __restrict__ Bm,
                                               float* __restrict__ C,
                                               int M, int N, int K) {
    __shared__ float As[16*132];  // [kk][row], padded
    __shared__ float Bs[16*132];  // [kk][col], padded
    int t  = threadIdx.x;
    int bm = blockIdx.y * 128, bn = blockIdx.x * 128;
    int ty = t >> 4, tx = t & 15;
    float acc[8][8];
#pragma unroll
    for (int i = 0; i < 8; i++)
#pragma unroll
        for (int j = 0; j < 8; j++) acc[i][j] = 0.f;

    for (int k0 = 0; k0 < K; k0 += 16) {
#pragma unroll
        for (int i = 0; i < 8; i++) {
            int idx = t + i * 256;          // 0..2047
            int r = idx >> 4, c = idx & 15; // A tile 128x16
            As[c*132 + r] = A[(size_t)(bm + r) * K + k0 + c];
        }
#pragma unroll
        for (int i = 0; i < 8; i++) {
            int idx = t + i * 256;
            int r = idx >> 7, c = idx & 127; // B tile 16x128
            Bs[r*132 + c] = Bm[(size_t)(k0 + r) * N + bn + c];
        }
        __syncthreads();
#pragma unroll
        for (int kk = 0; kk < 16; kk++) {
            float4 a0 = *(const float4*)&As[kk*132 + ty*8];
            float4 a1 = *(const float4*)&As[kk*132 + ty*8 + 4];
            float4 b0 = *(const float4*)&Bs[kk*132 + tx*8];
            float4 b1 = *(const float4*)&Bs[kk*132 + tx*8 + 4];
            float av[8] = {a0.x,a0.y,a0.z,a0.w,a1.x,a1.y,a1.z,a1.w};
            float bv[8] = {b0.x,b0.y,b0.z,b0.w,b1.x,b1.y,b1.z,b1.w};
#pragma unroll
            for (int i = 0; i < 8; i++)
#pragma unroll
                for (int j = 0; j < 8; j++)
                    acc[i][j] = fmaf(av[i], bv[j], acc[i][j]);
        }
        __syncthreads();
    }
#pragma unroll
    for (int i = 0; i < 8; i++) {
        float4 o0 = make_float4(acc[i][0],acc[i][1],acc[i][2],acc[i][3]);
        float4 o1 = make_float4(acc[i][4],acc[i][5],acc[i][6],acc[i][7]);
        size_t row = (size_t)(bm + ty*8 + i) * N + bn + tx*8;
        *(float4*)&C[row]     = o0;
        *(float4*)&C[row + 4] = o1;
    }
}

// ---------------- layernorm of k over DK (no scale/bias) ----------------
__global__ __launch_bounds__(256) void ln_k_kernel() {
    int row  = blockIdx.x * 8 + (threadIdx.x >> 5);  // (b*L+l)*H + h, 0..32767
    int lane = threadIdx.x & 31;
    int bl = row >> 4;
    int h  = row & 15;
    const float* kp = g_qkv + (size_t)bl * 3072 + 1024 + h * 64;
    float v0 = kp[lane], v1 = kp[lane + 32];
    float s = v0 + v1, ss = v0*v0 + v1*v1;
#pragma unroll
    for (int o = 16; o > 0; o >>= 1) {
        s  += __shfl_xor_sync(0xffffffffu, s,  o);
        ss += __shfl_xor_sync(0xffffffffu, ss, o);
    }
    float mu  = s * (1.f/64.f);
    float var = ss * (1.f/64.f) - mu*mu;
    float r   = rsqrtf(var + 1e-5f);
    float* o = g_kn + (size_t)bl * 1024 + h * 64;
    o[lane]      = (v0 - mu) * r;
    o[lane + 32] = (v1 - mu) * r;
}

// ---------------- causal flash attention (raw q, raw k, v) ----------------
// grid (B*H, L/64), 256 threads. QT=64 queries, KT=64 keys per tile.
#define ATTN_SMEM ((4*64*68 + 3*64)*4)
__global__ __launch_bounds__(256) void attn_kernel() {
    extern __shared__ float smf[];
    float* Qt = smf;              // [kk][qi], stride 68
    float* Kt = Qt + 64*68;       // [kk][jj], stride 68
    float* Vs = Kt + 64*68;       // [jj][dk], stride 68
    float* Ss = Vs + 64*68;       // [qi][jj], stride 68
    float* ms = Ss + 64*68;
    float* ls = ms + 64;
    float* cs = ls + 64;

    int bh = blockIdx.x; int b = bh >> 4; int h = bh & 15;
    int q0 = blockIdx.y * 64;
    int t  = threadIdx.x;

    for (int i = t; i < 4096; i += 256) {
        int r = i >> 6, c = i & 63;
        Qt[c*68 + r] = g_qkv[(size_t)(b*Lq + q0 + r) * 3072 + h*64 + c];
    }
    if (t < 64) { ms[t] = -1e30f; ls[t] = 0.f; }

    int ty = t >> 4, tx = t & 15;
    int qi0 = ty * 4, jj0 = tx * 4;     // S micro-tile owner
    int qi  = t >> 2, dk0 = (t & 3) * 16; // acc owner
    float acc[16];
#pragma unroll
    for (int m = 0; m < 16; m++) acc[m] = 0.f;
    __syncthreads();

    for (int j0 = 0; j0 <= q0; j0 += 64) {
        for (int i = t; i < 4096; i += 256) {
            int r = i >> 6, c = i & 63;
            size_t rowb = (size_t)(b*Lq + j0 + r) * 3072 + h*64 + c;
            Kt[c*68 + r] = g_qkv[rowb + 1024];
            Vs[r*68 + c] = g_qkv[rowb + 2048];
        }
        __syncthreads();

        float s4[4][4];
#pragma unroll
        for (int i = 0; i < 4; i++)
#pragma unroll
            for (int j = 0; j < 4; j++) s4[i][j] = 0.f;
        for (int kk = 0; kk < 64; kk++) {
            float4 a  = *(const float4*)&Qt[kk*68 + qi0];
            float4 bq = *(const float4*)&Kt[kk*68 + jj0];
            float av[4] = {a.x, a.y, a.z, a.w};
            float bv[4] = {bq.x, bq.y, bq.z, bq.w};
#pragma unroll
            for (int i = 0; i < 4; i++)
#pragma unroll
                for (int j = 0; j < 4; j++)
                    s4[i][j] = fmaf(av[i], bv[j], s4[i][j]);
        }
#pragma unroll
        for (int i = 0; i < 4; i++) {
            float vv[4];
#pragma unroll
            for (int j = 0; j < 4; j++) {
                float v = s4[i][j] * 0.125f;
                if (j0 + jj0 + j > q0 + qi0 + i) v = -1e30f;  // causal mask
                vv[j] = v;
            }
            *(float4*)&Ss[(qi0 + i)*68 + jj0] = make_float4(vv[0],vv[1],vv[2],vv[3]);
        }
        __syncthreads();

        if (t < 64) {  // per-row online-softmax bookkeeping
            float mold = ms[t];
            float mt = mold;
#pragma unroll
            for (int j = 0; j < 64; j++) mt = fmaxf(mt, Ss[t*68 + j]);
            float corr = __expf(mold - mt);
            float ssum = 0.f;
#pragma unroll
            for (int j = 0; j < 64; j++) {
                float p = __expf(Ss[t*68 + j] - mt);
                Ss[t*68 + j] = p;
                ssum += p;
            }
            ms[t] = mt; cs[t] = corr;
            ls[t] = ls[t] * corr + ssum;
        }
        __syncthreads();

        float corr = cs[qi];
#pragma unroll
        for (int m = 0; m < 16; m++) acc[m] *= corr;
        for (int jj = 0; jj < 64; jj++) {
            float p = Ss[qi*68 + jj];
            const float4* vp = (const float4*)&Vs[jj*68 + dk0];
            float4 v0 = vp[0], v1 = vp[1], v2 = vp[2], v3 = vp[3];
            float vv[16] = {v0.x,v0.y,v0.z,v0.w, v1.x,v1.y,v1.z,v1.w,
                            v2.x,v2.y,v2.z,v2.w, v3.x,v3.y,v3.z,v3.w};
#pragma unroll
            for (int m = 0; m < 16; m++) acc[m] = fmaf(p, vv[m], acc[m]);
        }
        __syncthreads();
    }
    float linv = 1.f / ls[qi];
    size_t ob = (size_t)(b*Lq + q0 + qi) * 1024 + h*64 + dk0;
#pragma unroll
    for (int m = 0; m < 16; m++) g_so[ob + m] = acc[m] * linv;
}

// ---------------- STP physics precompute ----------------
__global__ void stp_param_kernel(const float* __restrict__ W,   const float* __restrict__ Vgs,
                                 const float* __restrict__ VT0, const float* __restrict__ btau,
                                 const float* __restrict__ bgm, const float* __restrict__ Cch,
                                 const float* __restrict__ gam, const float* __restrict__ alpha,
                                 const float* __restrict__ ICt) {
    int idx = blockIdx.x * 256 + threadIdx.x;
    if (idx >= Hq*DKq*DKq) return;
    int h = idx >> 12;
    float veff = Vgs[h] - VT0[h] + W[idx];
    float sp   = (veff > 20.f) ? veff : log1pf(expf(veff));
    float gch  = btau[h] * sp;
    float invc = 1.f / Cch[h];
    float sig  = 1.f / (1.f + expf(-veff));
    float G    = bgm[h] * sp * sig;
    float smk  = tanhf(alpha[0] * (gch - ICt[0]));
    g_ret[idx]  = expf(-gch * invc);
    g_retC[idx] = expf(-gch * invc * (float)CHUNK);
    g_coef[idx] = gam[h] * smk * G;
}

// ---------------- STP scan pass A: chunk-local suffix sums ----------------
// F_end = r^C * F_start + A_chunk ; A built as A = r*A + coef*(v k^T), 128 steps.
__global__ __launch_bounds__(256) void stp_passA() {
    int bid = blockIdx.x;
    int c  = bid & (NC - 1);
    int bh = bid >> 3;
    int h  = bh & 15, b = bh >> 4;
    int t  = threadIdx.x;
    int d  = t >> 2, e0 = (t & 3) * 16;
    int pbase = h*4096 + d*64 + e0;
    float rr[16], cf[16], Aa[16];
#pragma unroll
    for (int i = 0; i < 16; i++) { rr[i]=g_ret[pbase+i]; cf[i]=g_coef[pbase+i]; Aa[i]=0.f; }
    __shared__ float sk[2][64], sv[2][64];
    int t0 = c * CHUNK;
    size_t kb = (size_t)(b*Lq + t0) * 1024 + h*64;
    size_t vb = (size_t)(b*Lq + t0) * 3072 + 2048 + h*64;
    if (t < 64)       sk[0][t]    = g_kn[kb + t];
    else if (t < 128) sv[0][t-64] = g_qkv[vb + (t - 64)];
    __syncthreads();
    for (int s = 0; s < CHUNK; s++) {
        int cur = s & 1;
        float nk = 0.f, nv = 0.f;
        if (s + 1 < CHUNK) {
            if (t < 64)       nk = g_kn [kb + (size_t)(s+1)*1024 + t];
            else if (t < 128) nv = g_qkv[vb + (size_t)(s+1)*3072 + (t - 64)];
        }
        float vd = sv[cur][d];
#pragma unroll
        for (int i = 0; i < 16; i++)
            Aa[i] = fmaf(rr[i], Aa[i], cf[i] * vd * sk[cur][e0 + i]);
        if (s + 1 < CHUNK) {
            if (t < 64)       sk[cur^1][t]    = nk;
            else if (t < 128) sv[cur^1][t-64] = nv;
        }
        __syncthreads();
    }
    float* out = g_A + (size_t)bid * 4096 + d*64 + e0;
#pragma unroll
    for (int i = 0; i < 16; i++) out[i] = Aa[i];
}

// ---------------- STP scan pass B: inter-chunk scan (tiny) ----------------
__global__ __launch_bounds__(256) void stp_passB() {
    int bh = blockIdx.x;
    int h  = bh & 15;
    int t  = threadIdx.x;
    int d = t >> 2, e0 = (t & 3) * 16;
    int pbase = h*4096 + d*64 + e0;
    float rc[16], F[16];
#pragma unroll
    for (int i = 0; i < 16; i++) { rc[i] = g_retC[pbase+i]; F[i] = 0.f; }
    size_t base = (size_t)bh * NC * 4096 + d*64 + e0;
    for (int c = 0; c < NC; c++) {
        float* fo = g_Fin + base + (size_t)c * 4096;
#pragma unroll
        for (int i = 0; i < 16; i++) fo[i] = F[i];
        if (c + 1 < NC) {
            const float* ai = g_A + base + (size_t)c * 4096;
#pragma unroll
            for (int i = 0; i < 16; i++) F[i] = fmaf(rc[i], F[i], ai[i]);
        }
    }
}

// ---------------- STP scan pass C: replay chunk, emit y, fuse gating ----------------
__global__ __launch_bounds__(256) void stp_passC(const float* __restrict__ WL,
                                                 const float* __restrict__ gate) {
    int bid = blockIdx.x;
    int c  = bid & (NC - 1);
    int bh = bid >> 3;
    int h  = bh & 15, b = bh >> 4;
    int t  = threadIdx.x;
    int d  = t >> 2, e0 = (t & 3) * 16;
    int pbase = h*4096 + d*64 + e0;
    float rr[16], cf[16], Wm[16], F[16];
#pragma unroll
    for (int i = 0; i < 16; i++) {
        rr[i] = g_ret[pbase+i]; cf[i] = g_coef[pbase+i]; Wm[i] = WL[pbase+i];
    }
    const float* fin = g_Fin + (size_t)bid * 4096 + d*64 + e0;
#pragma unroll
    for (int i = 0; i < 16; i++) F[i] = fin[i];
    float gct = 1.f / (1.f + expf(-gate[h]));
    __shared__ float sk[2][64], sv[2][64], sq[2][64];
    int t0 = c * CHUNK;
    size_t kb = (size_t)(b*Lq + t0) * 1024 + h*64;   // also g_so / g_ymix base layout
    size_t qb = (size_t)(b*Lq + t0) * 3072 + h*64;
    bool lead = (t & 3) == 0;
    if (t < 64)       sk[0][t]     = g_kn [kb + t];
    else if (t < 128) sv[0][t-64]  = g_qkv[qb + 2048 + (t - 64)];
    else if (t < 192) sq[0][t-128] = g_qkv[qb + (t - 128)];
    float so_cur = 0.f;
    size_t sob = kb + d;
    if (lead) so_cur = g_so[sob];
    __syncthreads();
    for (int s = 0; s < CHUNK; s++) {
        int cur = s & 1;
        float nk = 0.f, nv = 0.f, nq = 0.f, nso = 0.f;
        if (s + 1 < CHUNK) {
            if (t < 64)       nk = g_kn [kb + (size_t)(s+1)*1024 + t];
            else if (t < 128) nv = g_qkv[qb + (size_t)(s+1)*3072 + 2048 + (t - 64)];
            else if (t < 192) nq = g_qkv[qb + (size_t)(s+1)*3072 + (t - 128)];
            if (lead)         nso = g_so[sob + (size_t)(s+1)*1024];
        }
        float vd = sv[cur][d];
        float y = 0.f;
#pragma unroll
        for (int i = 0; i < 16; i++) {
            float Fi = fmaf(rr[i], F[i], cf[i] * vd * sk[cur][e0 + i]);
            F[i] = Fi;
            y = fmaf(Wm[i] + Fi, sq[cur][e0 + i], y);
        }
        y += __shfl_down_sync(0xffffffffu, y, 2);
        y += __shfl_down_sync(0xffffffffu, y, 1);
        if (lead) {
            g_ymix[sob + (size_t)s * 1024] = gct * so_cur + (1.f - gct) * y;
            so_cur = nso;
        }
        if (s + 1 < CHUNK) {
            if (t < 64)       sk[cur^1][t]     = nk;
            else if (t < 128) sv[cur^1][t-64]  = nv;
            else if (t < 192) sq[cur^1][t-128] = nq;
        }
        __syncthreads();
    }
}

// ---------------- launch ----------------
extern "C" void kernel_launch(void* const* d_in, const int* in_sizes, int n_in,
                              void* d_out, int out_size) {
    const float* x     = (const float*)d_in[0];
    const float* Wqkv  = (const float*)d_in[1];
    const float* Wo    = (const float*)d_in[2];
    const float* WLTM  = (const float*)d_in[3];
    const float* Vgs   = (const float*)d_in[4];
    const float* VT0   = (const float*)d_in[5];
    const float* btau  = (const float*)d_in[6];
    const float* bgm   = (const float*)d_in[7];
    const float* Cch   = (const float*)d_in[8];
    const float* gam   = (const float*)d_in[9];
    const float* alpha = (const float*)d_in[10];
    const float* ICt   = (const float*)d_in[11];
    const float* gate  = (const float*)d_in[12];
    float* out = (float*)d_out;

    float *qkvp, *ymixp;
    cudaGetSymbolAddress((void**)&qkvp,  g_qkv);
    cudaGetSymbolAddress((void**)&ymixp, g_ymix);
    cudaFuncSetAttribute(attn_kernel, cudaFuncAttributeMaxDynamicSharedMemorySize, ATTN_SMEM);

    // 1) qkv = x @ W_qkv        [2048,1024] x [1024,3072]
    gemm128<<<dim3(24, 16), 256>>>(x, Wqkv, qkvp, 2048, 3072, 1024);
    // 2) layernorm(k)
    ln_k_kernel<<<4096, 256>>>();
    // 3) STP coefficient precompute
    stp_param_kernel<<<(Hq*DKq*DKq + 255)/256, 256>>>(WLTM, Vgs, VT0, btau, bgm, Cch, gam, alpha, ICt);
    // 4) causal softmax attention (raw q,k,v)
    attn_kernel<<<dim3(Bq*Hq, Lq/64), 256, ATTN_SMEM>>>();
    // 5-7) chunked linear-recurrence scan + gated mix
    stp_passA<<<Bq*Hq*NC, 256>>>();
    stp_passB<<<Bq*Hq, 256>>>();
    stp_passC<<<Bq*Hq*NC, 256>>>(WLTM, gate);
    // 8) out = ymix @ W_o       [2048,1024] x [1024,1024]
    gemm128<<<dim3(8, 16), 256>>>(ymixp, Wo, out, 2048, 1024, 1024);
}

// round 2
// speedup vs baseline: 1.1663x; 1.1663x over previous
#include <cuda_runtime.h>
#include <math.h>

#define Bq 2
#define Lq 1024
#define Dq 1024
#define Hq 16
#define DKq 64
#define CHUNK 128
#define NC (Lq/CHUNK)   /* 8 */

typedef unsigned long long u64;

// ---------------- f32x2 packed-math helpers (sm_100+ PTX) ----------------
__device__ __forceinline__ u64 pk2(float lo, float hi) {
    u64 r; asm("mov.b64 %0, {%1, %2};" : "=l"(r) : "f"(lo), "f"(hi)); return r;
}
__device__ __forceinline__ u64 dup2(float v) { return pk2(v, v); }
__device__ __forceinline__ void upk2(u64 x, float& lo, float& hi) {
    asm("mov.b64 {%0, %1}, %2;" : "=f"(lo), "=f"(hi) : "l"(x));
}
__device__ __forceinline__ u64 fma2(u64 a, u64 b, u64 c) {
    u64 d; asm("fma.rn.f32x2 %0, %1, %2, %3;" : "=l"(d) : "l"(a), "l"(b), "l"(c)); return d;
}
__device__ __forceinline__ u64 mul2(u64 a, u64 b) {
    u64 d; asm("mul.rn.f32x2 %0, %1, %2;" : "=l"(d) : "l"(a), "l"(b)); return d;
}

// ---------------- scratch (device globals; no allocation allowed) ----------------
__device__ float g_qkv [Bq*Lq*3*Dq];       // [b,l, {q|k|v} blocks of 1024]
__device__ float g_kn  [Bq*Lq*Dq];         // layernormed k, [b,l,h,dk]
__device__ float g_so  [Bq*Lq*Dq];         // softmax attention out, [b,l,h,dk]
__device__ float g_ymix[Bq*Lq*Dq];         // gated mix, [b,l,d]
__device__ float g_ret [Hq*DKq*DKq];
__device__ float g_coef[Hq*DKq*DKq];
__device__ float g_retC[Hq*DKq*DKq];       // retention^CHUNK
__device__ float g_A   [Bq*Hq*NC*DKq*DKq]; // chunk-local suffix sums
__device__ float g_Fin [Bq*Hq*NC*DKq*DKq]; // F at chunk starts

// ---------------- fp32 GEMM with f32x2 FMA + reg double-buffer ----------------
// C[M,N] = A[M,K] @ B[K,N]; 128x128x16 tiles, 256 threads, 8x8 micro (4x f32x2-pairs x 8).
__global__ __launch_bounds__(256) void gemm128(const float* __restrict__ A,
                                               const float* __restrict__ Bm,
                                               float* __restrict__ C,
                                               int M, int N, int K) {
    __shared__ float As[16*132];  // [kk][row]
    __shared__ float Bs[16*132];  // [kk][col]
    int t  = threadIdx.x;
    int bm = blockIdx.y * 128, bn = blockIdx.x * 128;
    int ty = t >> 4, tx = t & 15;
    int ty8 = ty * 8, tx8 = tx * 8;

    u64 acc2[4][8];
#pragma unroll
    for (int i = 0; i < 4; i++)
#pragma unroll
        for (int j = 0; j < 8; j++) acc2[i][j] = 0ull;

    // A load map: ra[i] = A[bm + ty + 16i][k0 + tx]  -> As[tx*132 + ty + 16i]
    // B load map: rb[i] = B[k0 + (t>>7) + 2i][bn + (t&127)] -> Bs[((t>>7)+2i)*132 + (t&127)]
    float ra[8], rb[8];
    const float* Arow = A + (size_t)(bm + ty) * K + tx;
    const float* Brow = Bm + (size_t)(t >> 7) * N + bn + (t & 127);
#pragma unroll
    for (int i = 0; i < 8; i++) {
        ra[i] = Arow[(size_t)(16 * i) * K];
        rb[i] = Brow[(size_t)(2 * i) * N];
    }
    {
#pragma unroll
        for (int i = 0; i < 8; i++) {
            As[tx*132 + ty + 16*i] = ra[i];
            Bs[((t>>7) + 2*i)*132 + (t & 127)] = rb[i];
        }
    }
    __syncthreads();

    for (int k0 = 0; k0 < K; k0 += 16) {
        bool more = (k0 + 16) < K;
        if (more) {
            const float* An = Arow + (k0 + 16);
            const float* Bn = Brow + (size_t)(k0 + 16) * N;
#pragma unroll
            for (int i = 0; i < 8; i++) {
                ra[i] = An[(size_t)(16 * i) * K];
                rb[i] = Bn[(size_t)(2 * i) * N];
            }
        }
#pragma unroll
        for (int kk = 0; kk < 16; kk++) {
            u64 a2[4];
#pragma unroll
            for (int i2 = 0; i2 < 4; i2++)
                a2[i2] = *(const u64*)&As[kk*132 + ty8 + 2*i2];
            float4 b0 = *(const float4*)&Bs[kk*132 + tx8];
            float4 b1 = *(const float4*)&Bs[kk*132 + tx8 + 4];
            u64 bd[8] = {dup2(b0.x), dup2(b0.y), dup2(b0.z), dup2(b0.w),
                         dup2(b1.x), dup2(b1.y), dup2(b1.z), dup2(b1.w)};
#pragma unroll
            for (int i2 = 0; i2 < 4; i2++)
#pragma unroll
                for (int j = 0; j < 8; j++)
                    acc2[i2][j] = fma2(a2[i2], bd[j], acc2[i2][j]);
        }
        __syncthreads();
        if (more) {
#pragma unroll
            for (int i = 0; i < 8; i++) {
                As[tx*132 + ty + 16*i] = ra[i];
                Bs[((t>>7) + 2*i)*132 + (t & 127)] = rb[i];
            }
            __syncthreads();
        }
    }
#pragma unroll
    for (int i2 = 0; i2 < 4; i2++) {
        float lo[8], hi[8];
#pragma unroll
        for (int j = 0; j < 8; j++) upk2(acc2[i2][j], lo[j], hi[j]);
        size_t r0 = (size_t)(bm + ty8 + 2*i2) * N + bn + tx8;
        *(float4*)&C[r0]         = make_float4(lo[0], lo[1], lo[2], lo[3]);
        *(float4*)&C[r0 + 4]     = make_float4(lo[4], lo[5], lo[6], lo[7]);
        *(float4*)&C[r0 + N]     = make_float4(hi[0], hi[1], hi[2], hi[3]);
        *(float4*)&C[r0 + N + 4] = make_float4(hi[4], hi[5], hi[6], hi[7]);
    }
}

// ---------------- layernorm of k over DK ----------------
__global__ __launch_bounds__(256) void ln_k_kernel() {
    int row  = blockIdx.x * 8 + (threadIdx.x >> 5);
    int lane = threadIdx.x & 31;
    int bl = row >> 4;
    int h  = row & 15;
    const float* kp = g_qkv + (size_t)bl * 3072 + 1024 + h * 64;
    float v0 = kp[lane], v1 = kp[lane + 32];
    float s = v0 + v1, ss = v0*v0 + v1*v1;
#pragma unroll
    for (int o = 16; o > 0; o >>= 1) {
        s  += __shfl_xor_sync(0xffffffffu, s,  o);
        ss += __shfl_xor_sync(0xffffffffu, ss, o);
    }
    float mu  = s * (1.f/64.f);
    float var = ss * (1.f/64.f) - mu*mu;
    float r   = rsqrtf(var + 1e-5f);
    float* o = g_kn + (size_t)bl * 1024 + h * 64;
    o[lane]      = (v0 - mu) * r;
    o[lane + 32] = (v1 - mu) * r;
}

// ---------------- causal flash attention: QT=128, KT=64, 256 threads ----------------
// Micro-tiles: S stage 8(qi, f32x2-paired)x4(jj); PV stage 8(qi)x4(dk).
// P stored transposed Ps[jj][qi] so PV reads are float2/float4 rows.
#define ATTN_SMEM ((64*132 + 64*68 + 64*68 + 64*132 + 256)*4)
__global__ __launch_bounds__(256) void attn_kernel() {
    extern __shared__ float smf[];
    float* Qt = smf;              // [kk][qi]  64 x 132
    float* Kt = Qt + 64*132;      // [kk][jj]  64 x 68
    float* Vs = Kt + 64*68;       // [jj][dk]  64 x 68
    float* Ps = Vs + 64*68;       // [jj][qi]  64 x 132
    float* ms = Ps + 64*132;      // [128]
    float* ls = ms + 128;         // [128]

    int bh = blockIdx.x; int b = bh >> 4; int h = bh & 15;
    int q0 = (7 - blockIdx.y) * 128;    // heavy blocks first
    int t  = threadIdx.x;
    int ty = t >> 4, tx = t & 15;
    int qi0 = ty * 8;                   // 8 query rows per thread
    int jj0 = tx * 4, dk0 = tx * 4;

    // load Q transposed (vectorized global reads, scalar transposed STS)
    for (int i = t; i < 2048; i += 256) {
        int r = i >> 4, c = (i & 15) * 4;
        float4 qv = *(const float4*)&g_qkv[(size_t)(b*Lq + q0 + r) * 3072 + h*64 + c];
        Qt[(c+0)*132 + r] = qv.x; Qt[(c+1)*132 + r] = qv.y;
        Qt[(c+2)*132 + r] = qv.z; Qt[(c+3)*132 + r] = qv.w;
    }
    if (t < 128) { ms[t] = -1e30f; ls[t] = 0.f; }

    u64 acc2[4][4];
#pragma unroll
    for (int i = 0; i < 4; i++)
#pragma unroll
        for (int j = 0; j < 4; j++) acc2[i][j] = 0ull;
    __syncthreads();

    int ntiles = q0 / 64 + 2;
    for (int tile = 0; tile < ntiles; tile++) {
        int j0 = tile * 64;
        // load K (transposed) and V
        for (int i = t; i < 1024; i += 256) {
            int r = i >> 4, c = (i & 15) * 4;
            size_t base = (size_t)(b*Lq + j0 + r) * 3072 + h*64 + c;
            float4 kv = *(const float4*)&g_qkv[base + 1024];
            float4 vv = *(const float4*)&g_qkv[base + 2048];
            Kt[(c+0)*68 + r] = kv.x; Kt[(c+1)*68 + r] = kv.y;
            Kt[(c+2)*68 + r] = kv.z; Kt[(c+3)*68 + r] = kv.w;
            *(float4*)&Vs[r*68 + c] = vv;
        }
        __syncthreads();

        // ---- S = Q K^T (8x4 per thread, qi packed in f32x2) ----
        u64 s2[4][4];
#pragma unroll
        for (int i = 0; i < 4; i++)
#pragma unroll
            for (int j = 0; j < 4; j++) s2[i][j] = 0ull;
#pragma unroll 8
        for (int kk = 0; kk < 64; kk++) {
            const float* qrow = &Qt[kk*132 + qi0];
            u64 q2[4];
#pragma unroll
            for (int i2 = 0; i2 < 4; i2++) q2[i2] = *(const u64*)(qrow + 2*i2);
            float4 kv = *(const float4*)&Kt[kk*68 + jj0];
            u64 kd[4] = {dup2(kv.x), dup2(kv.y), dup2(kv.z), dup2(kv.w)};
#pragma unroll
            for (int i2 = 0; i2 < 4; i2++)
#pragma unroll
                for (int j = 0; j < 4; j++)
                    s2[i2][j] = fma2(q2[i2], kd[j], s2[i2][j]);
        }
        // unpack + scale + mask
        float sv[8][4];
#pragma unroll
        for (int i2 = 0; i2 < 4; i2++)
#pragma unroll
            for (int j = 0; j < 4; j++) {
                float lo, hi; upk2(s2[i2][j], lo, hi);
                sv[2*i2][j] = lo * 0.125f; sv[2*i2+1][j] = hi * 0.125f;
            }
        if (j0 >= q0) {
#pragma unroll
            for (int i = 0; i < 8; i++)
#pragma unroll
                for (int j = 0; j < 4; j++)
                    if (j0 + jj0 + j > q0 + qi0 + i) sv[i][j] = -1e30f;
        }
        // ---- distributed online softmax (16-lane row groups) ----
        float p[8][4], corr[8];
#pragma unroll
        for (int i = 0; i < 8; i++) {
            int r = qi0 + i;
            float mold = ms[r];
            float mx = fmaxf(fmaxf(sv[i][0], sv[i][1]), fmaxf(sv[i][2], sv[i][3]));
#pragma unroll
            for (int o = 1; o < 16; o <<= 1)
                mx = fmaxf(mx, __shfl_xor_sync(0xffffffffu, mx, o));
            float mt = fmaxf(mold, mx);
            float sum = 0.f;
#pragma unroll
            for (int j = 0; j < 4; j++) {
                float e = __expf(sv[i][j] - mt);
                p[i][j] = e; sum += e;
            }
#pragma unroll
            for (int o = 1; o < 16; o <<= 1)
                sum += __shfl_xor_sync(0xffffffffu, sum, o);
            corr[i] = __expf(mold - mt);
            if (tx == 0) { ms[r] = mt; ls[r] = ls[r] * corr[i] + sum; }
        }
        // write P transposed: Ps[jj][qi]
#pragma unroll
        for (int j = 0; j < 4; j++) {
            *(float4*)&Ps[(jj0+j)*132 + qi0]     = make_float4(p[0][j], p[1][j], p[2][j], p[3][j]);
            *(float4*)&Ps[(jj0+j)*132 + qi0 + 4] = make_float4(p[4][j], p[5][j], p[6][j], p[7][j]);
        }
        __syncthreads();

        // ---- rescale + PV accumulate ----
        u64 corr2[4] = {pk2(corr[0], corr[1]), pk2(corr[2], corr[3]),
                        pk2(corr[4], corr[5]), pk2(corr[6], corr[7])};
#pragma unroll
        for (int i2 = 0; i2 < 4; i2++)
#pragma unroll
            for (int j = 0; j < 4; j++)
                acc2[i2][j] = mul2(acc2[i2][j], corr2[i2]);
#pragma unroll 8
        for (int jj = 0; jj < 64; jj++) {
            const float* prow = &Ps[jj*132 + qi0];
            u64 p2[4];
#pragma unroll
            for (int i2 = 0; i2 < 4; i2++) p2[i2] = *(const u64*)(prow + 2*i2);
            float4 vv = *(const float4*)&Vs[jj*68 + dk0];
            u64 vd[4] = {dup2(vv.x), dup2(vv.y), dup2(vv.z), dup2(vv.w)};
#pragma unroll
            for (int i2 = 0; i2 < 4; i2++)
#pragma unroll
                for (int j = 0; j < 4; j++)
                    acc2[i2][j] = fma2(p2[i2], vd[j], acc2[i2][j]);
        }
        __syncthreads();
    }
    // epilogue: normalize by l, store
#pragma unroll
    for (int i2 = 0; i2 < 4; i2++) {
        float lo[4], hi[4];
#pragma unroll
        for (int j = 0; j < 4; j++) upk2(acc2[i2][j], lo[j], hi[j]);
        float l0 = 1.f / ls[qi0 + 2*i2], l1 = 1.f / ls[qi0 + 2*i2 + 1];
        size_t o0 = (size_t)(b*Lq + q0 + qi0 + 2*i2) * 1024 + h*64 + dk0;
        *(float4*)&g_so[o0]        = make_float4(lo[0]*l0, lo[1]*l0, lo[2]*l0, lo[3]*l0);
        *(float4*)&g_so[o0 + 1024] = make_float4(hi[0]*l1, hi[1]*l1, hi[2]*l1, hi[3]*l1);
    }
}

// ---------------- STP physics precompute ----------------
__global__ void stp_param_kernel(const float* __restrict__ W,   const float* __restrict__ Vgs,
                                 const float* __restrict__ VT0, const float* __restrict__ btau,
                                 const float* __restrict__ bgm, const float* __restrict__ Cch,
                                 const float* __restrict__ gam, const float* __restrict__ alpha,
                                 const float* __restrict__ ICt) {
    int idx = blockIdx.x * 256 + threadIdx.x;
    if (idx >= Hq*DKq*DKq) return;
    int h = idx >> 12;
    float veff = Vgs[h] - VT0[h] + W[idx];
    float sp   = (veff > 20.f) ? veff : log1pf(expf(veff));
    float gch  = btau[h] * sp;
    float invc = 1.f / Cch[h];
    float sig  = 1.f / (1.f + expf(-veff));
    float G    = bgm[h] * sp * sig;
    float smk  = tanhf(alpha[0] * (gch - ICt[0]));
    g_ret[idx]  = expf(-gch * invc);
    g_retC[idx] = expf(-gch * invc * (float)CHUNK);
    g_coef[idx] = gam[h] * smk * G;
}

// ---------------- STP scan pass A: chunk-local suffix sums ----------------
__global__ __launch_bounds__(256) void stp_passA() {
    int bid = blockIdx.x;
    int c  = bid & (NC - 1);
    int bh = bid >> 3;
    int h  = bh & 15, b = bh >> 4;
    int t  = threadIdx.x;
    int d  = t >> 2, e0 = (t & 3) * 16;
    int pbase = h*4096 + d*64 + e0;
    float rr[16], cf[16], Aa[16];
#pragma unroll
    for (int i = 0; i < 16; i++) { rr[i]=g_ret[pbase+i]; cf[i]=g_coef[pbase+i]; Aa[i]=0.f; }
    __shared__ float sk[2][64], sv[2][64];
    int t0 = c * CHUNK;
    size_t kb = (size_t)(b*Lq + t0) * 1024 + h*64;
    size_t vb = (size_t)(b*Lq + t0) * 3072 + 2048 + h*64;
    if (t < 64)       sk[0][t]    = g_kn[kb + t];
    else if (t < 128) sv[0][t-64] = g_qkv[vb + (t - 64)];
    __syncthreads();
    for (int s = 0; s < CHUNK; s++) {
        int cur = s & 1;
        float nk = 0.f, nv = 0.f;
        if (s + 1 < CHUNK) {
            if (t < 64)       nk = g_kn [kb + (size_t)(s+1)*1024 + t];
            else if (t < 128) nv = g_qkv[vb + (size_t)(s+1)*3072 + (t - 64)];
        }
        float vd = sv[cur][d];
#pragma unroll
        for (int i = 0; i < 16; i++)
            Aa[i] = fmaf(rr[i], Aa[i], cf[i] * vd * sk[cur][e0 + i]);
        if (s + 1 < CHUNK) {
            if (t < 64)       sk[cur^1][t]    = nk;
            else if (t < 128) sv[cur^1][t-64] = nv;
        }
        __syncthreads();
    }
    float* out = g_A + (size_t)bid * 4096 + d*64 + e0;
#pragma unroll
    for (int i = 0; i < 16; i++) out[i] = Aa[i];
}

// ---------------- STP scan pass B: inter-chunk scan ----------------
__global__ __launch_bounds__(256) void stp_passB() {
    int bh = blockIdx.x;
    int h  = bh & 15;
    int t  = threadIdx.x;
    int d = t >> 2, e0 = (t & 3) * 16;
    int pbase = h*4096 + d*64 + e0;
    float rc[16], F[16];
#pragma unroll
    for (int i = 0; i < 16; i++) { rc[i] = g_retC[pbase+i]; F[i] = 0.f; }
    size_t base = (size_t)bh * NC * 4096 + d*64 + e0;
    for (int c = 0; c < NC; c++) {
        float* fo = g_Fin + base + (size_t)c * 4096;
#pragma unroll
        for (int i = 0; i < 16; i++) fo[i] = F[i];
        if (c + 1 < NC) {
            const float* ai = g_A + base + (size_t)c * 4096;
#pragma unroll
            for (int i = 0; i < 16; i++) F[i] = fmaf(rc[i], F[i], ai[i]);
        }
    }
}

// ---------------- STP scan pass C: replay chunk, emit y, fuse gating ----------------
__global__ __launch_bounds__(256) void stp_passC(const float* __restrict__ WL,
                                                 const float* __restrict__ gate) {
    int bid = blockIdx.x;
    int c  = bid & (NC - 1);
    int bh = bid >> 3;
    int h  = bh & 15, b = bh >> 4;
    int t  = threadIdx.x;
    int d  = t >> 2, e0 = (t & 3) * 16;
    int pbase = h*4096 + d*64 + e0;
    float rr[16], cf[16], Wm[16], F[16];
#pragma unroll
    for (int i = 0; i < 16; i++) {
        rr[i] = g_ret[pbase+i]; cf[i] = g_coef[pbase+i]; Wm[i] = WL[pbase+i];
    }
    const float* fin = g_Fin + (size_t)bid * 4096 + d*64 + e0;
#pragma unroll
    for (int i = 0; i < 16; i++) F[i] = fin[i];
    float gct = 1.f / (1.f + expf(-gate[h]));
    __shared__ float sk[2][64], sv[2][64], sq[2][64];
    int t0 = c * CHUNK;
    size_t kb = (size_t)(b*Lq + t0) * 1024 + h*64;
    size_t qb = (size_t)(b*Lq + t0) * 3072 + h*64;
    bool lead = (t & 3) == 0;
    if (t < 64)       sk[0][t]     = g_kn [kb + t];
    else if (t < 128) sv[0][t-64]  = g_qkv[qb + 2048 + (t - 64)];
    else if (t < 192) sq[0][t-128] = g_qkv[qb + (t - 128)];
    float so_cur = 0.f;
    size_t sob = kb + d;
    if (lead) so_cur = g_so[sob];
    __syncthreads();
    for (int s = 0; s < CHUNK; s++) {
        int cur = s & 1;
        float nk = 0.f, nv = 0.f, nq = 0.f, nso = 0.f;
        if (s + 1 < CHUNK) {
            if (t < 64)       nk = g_kn [kb + (size_t)(s+1)*1024 + t];
            else if (t < 128) nv = g_qkv[qb + (size_t)(s+1)*3072 + 2048 + (t - 64)];
            else if (t < 192) nq = g_qkv[qb + (size_t)(s+1)*3072 + (t - 128)];
            if (lead)         nso = g_so[sob + (size_t)(s+1)*1024];
        }
        float vd = sv[cur][d];
        float y = 0.f;
#pragma unroll
        for (int i = 0; i < 16; i++) {
            float Fi = fmaf(rr[i], F[i], cf[i] * vd * sk[cur][e0 + i]);
            F[i] = Fi;
            y = fmaf(Wm[i] + Fi, sq[cur][e0 + i], y);
        }
        y += __shfl_down_sync(0xffffffffu, y, 2);
        y += __shfl_down_sync(0xffffffffu, y, 1);
        if (lead) {
            g_ymix[sob + (size_t)s * 1024] = gct * so_cur + (1.f - gct) * y;
            so_cur = nso;
        }
        if (s + 1 < CHUNK) {
            if (t < 64)       sk[cur^1][t]     = nk;
            else if (t < 128) sv[cur^1][t-64]  = nv;
            else if (t < 192) sq[cur^1][t-128] = nq;
        }
        __syncthreads();
    }
}

// ---------------- launch ----------------
extern "C" void kernel_launch(void* const* d_in, const int* in_sizes, int n_in,
                              void* d_out, int out_size) {
    const float* x     = (const float*)d_in[0];
    const float* Wqkv  = (const float*)d_in[1];
    const float* Wo    = (const float*)d_in[2];
    const float* WLTM  = (const float*)d_in[3];
    const float* Vgs   = (const float*)d_in[4];
    const float* VT0   = (const float*)d_in[5];
    const float* btau  = (const float*)d_in[6];
    const float* bgm   = (const float*)d_in[7];
    const float* Cch   = (const float*)d_in[8];
    const float* gam   = (const float*)d_in[9];
    const float* alpha = (const float*)d_in[10];
    const float* ICt   = (const float*)d_in[11];
    const float* gate  = (const float*)d_in[12];
    float* out = (float*)d_out;

    float *qkvp, *ymixp;
    cudaGetSymbolAddress((void**)&qkvp,  g_qkv);
    cudaGetSymbolAddress((void**)&ymixp, g_ymix);
    cudaFuncSetAttribute(attn_kernel, cudaFuncAttributeMaxDynamicSharedMemorySize, ATTN_SMEM);

    // 1) qkv = x @ W_qkv        [2048,1024] x [1024,3072]
    gemm128<<<dim3(24, 16), 256>>>(x, Wqkv, qkvp, 2048, 3072, 1024);
    // 2) layernorm(k)
    ln_k_kernel<<<4096, 256>>>();
    // 3) STP coefficient precompute
    stp_param_kernel<<<(Hq*DKq*DKq + 255)/256, 256>>>(WLTM, Vgs, VT0, btau, bgm, Cch, gam, alpha, ICt);
    // 4) causal softmax attention (raw q,k,v), QT=128 tiles, heavy blocks first
    attn_kernel<<<dim3(Bq*Hq, Lq/128), 256, ATTN_SMEM>>>();
    // 5-7) chunked linear-recurrence scan + gated mix
    stp_passA<<<Bq*Hq*NC, 256>>>();
    stp_passB<<<Bq*Hq, 256>>>();
    stp_passC<<<Bq*Hq*NC, 256>>>(WLTM, gate);
    // 8) out = ymix @ W_o       [2048,1024] x [1024,1024]
    gemm128<<<dim3(8, 16), 256>>>(ymixp, Wo, out, 2048, 1024, 1024);
}

// round 4
// speedup vs baseline: 2.0733x; 1.7776x over previous
#include <cuda_runtime.h>
#include <cuda_bf16.h>
#include <math.h>
#include <stdint.h>

#define Bq 2
#define Lq 1024
#define Dq 1024
#define Hq 16
#define DKq 64
#define CHUNK 128
#define NC (Lq/CHUNK)   /* 8 */

typedef unsigned long long u64;

// ---------------- f32x2 packed-math helpers ----------------
__device__ __forceinline__ u64 pk2(float lo, float hi) {
    u64 r; asm("mov.b64 %0, {%1, %2};" : "=l"(r) : "f"(lo), "f"(hi)); return r;
}
__device__ __forceinline__ u64 dup2(float v) { return pk2(v, v); }
__device__ __forceinline__ void upk2(u64 x, float& lo, float& hi) {
    asm("mov.b64 {%0, %1}, %2;" : "=f"(lo), "=f"(hi) : "l"(x));
}
__device__ __forceinline__ u64 fma2(u64 a, u64 b, u64 c) {
    u64 d; asm("fma.rn.f32x2 %0, %1, %2, %3;" : "=l"(d) : "l"(a), "l"(b), "l"(c)); return d;
}
__device__ __forceinline__ u64 mul2(u64 a, u64 b) {
    u64 d; asm("mul.rn.f32x2 %0, %1, %2;" : "=l"(d) : "l"(a), "l"(b)); return d;
}

// ---------------- warp-mma helpers (baseline PTX; no 'a' features) ----------------
__device__ __forceinline__ uint32_t smem_u32(const void* p) {
    uint32_t a;
    asm("{ .reg .u64 t; cvta.to.shared.u64 t, %1; cvt.u32.u64 %0, t; }" : "=r"(a) : "l"(p));
    return a;
}
__device__ __forceinline__ void ldmx4(uint32_t* r, uint32_t addr) {
    asm volatile("ldmatrix.sync.aligned.m8n8.x4.shared.b16 {%0,%1,%2,%3}, [%4];"
        : "=r"(r[0]), "=r"(r[1]), "=r"(r[2]), "=r"(r[3]) : "r"(addr));
}
__device__ __forceinline__ void mma16816(float* c, const uint32_t* a, uint32_t b0, uint32_t b1) {
    asm volatile("mma.sync.aligned.m16n8k16.row.col.f32.bf16.bf16.f32 "
        "{%0,%1,%2,%3}, {%4,%5,%6,%7}, {%8,%9}, {%0,%1,%2,%3};"
        : "+f"(c[0]), "+f"(c[1]), "+f"(c[2]), "+f"(c[3])
        : "r"(a[0]), "r"(a[1]), "r"(a[2]), "r"(a[3]), "r"(b0), "r"(b1));
}

// ---------------- scratch ----------------
__device__ float g_qkv  [Bq*Lq*3*Dq];
__device__ float g_kn   [Bq*Lq*Dq];
__device__ float g_so   [Bq*Lq*Dq];
__device__ __nv_bfloat16 g_xh   [Bq*Lq*Dq];
__device__ __nv_bfloat16 g_xl   [Bq*Lq*Dq];
__device__ __nv_bfloat16 g_ymh  [Bq*Lq*Dq];
__device__ __nv_bfloat16 g_yml  [Bq*Lq*Dq];
__device__ __nv_bfloat16 g_wqh  [3*Dq*Dq];   // W_qkv^T hi  [3072][1024]
__device__ __nv_bfloat16 g_wql  [3*Dq*Dq];
__device__ __nv_bfloat16 g_woh  [Dq*Dq];     // W_o^T hi [1024][1024]
__device__ __nv_bfloat16 g_wol  [Dq*Dq];
__device__ float g_ret  [Hq*DKq*DKq];
__device__ float g_coef [Hq*DKq*DKq];
__device__ float g_retC [Hq*DKq*DKq];
__device__ float g_A    [Bq*Hq*NC*DKq*DKq];
__device__ float g_Fin  [Bq*Hq*NC*DKq*DKq];

// ---------------- prep: plain bf16 hi/lo split ----------------
__global__ __launch_bounds__(256) void split_plain(const float* __restrict__ s,
                                                   __nv_bfloat16* __restrict__ dh,
                                                   __nv_bfloat16* __restrict__ dl, int n) {
    int i = blockIdx.x * 1024 + threadIdx.x * 4;
    if (i >= n) return;
    float4 v = *(const float4*)&s[i];
    float vs[4] = {v.x, v.y, v.z, v.w};
#pragma unroll
    for (int j = 0; j < 4; j++) {
        __nv_bfloat16 h = __float2bfloat16_rn(vs[j]);
        dh[i + j] = h;
        dl[i + j] = __float2bfloat16_rn(vs[j] - __bfloat162float(h));
    }
}

// ---------------- prep: transpose + split:  dst[c][r] = split(src[r][c]) ----------------
__global__ __launch_bounds__(256) void transpose_split(const float* __restrict__ src,
                                                       __nv_bfloat16* __restrict__ dh,
                                                       __nv_bfloat16* __restrict__ dl,
                                                       int R, int C) {
    __shared__ float tile[32][33];
    int c0 = blockIdx.x * 32, r0 = blockIdx.y * 32;
    int tx = threadIdx.x & 31, ty = threadIdx.x >> 5;
#pragma unroll
    for (int i = 0; i < 4; i++)
        tile[ty + 8*i][tx] = src[(size_t)(r0 + ty + 8*i) * C + c0 + tx];
    __syncthreads();
#pragma unroll
    for (int i = 0; i < 4; i++) {
        float v = tile[tx][ty + 8*i];
        __nv_bfloat16 h = __float2bfloat16_rn(v);
        size_t o = (size_t)(c0 + ty + 8*i) * R + r0 + tx;
        dh[o] = h;
        dl[o] = __float2bfloat16_rn(v - __bfloat162float(h));
    }
}

// ---------------- bf16 split-GEMM on mma.sync: C[M,N] = (Ah+Al)[M,K] @ (Bh+Bl)[N,K]^T ----------------
// CTA 128x128, warp 64x32, k16 chunks, double-buffered smem.
// smem unit layout: unit u (= row*2 + kgroup) at byte off u*16 + ((u>>3)<<4)  (ldmatrix conflict-free)
#define GST 18432           /* per-stage bytes: 4 regions x 4608 */
#define GEMM_SMEM (2*GST)
__device__ __forceinline__ uint32_t uoff(uint32_t u) { return u*16u + ((u >> 3) << 4); }

__global__ __launch_bounds__(256) void gemm_bf16(const __nv_bfloat16* __restrict__ Ah,
                                                 const __nv_bfloat16* __restrict__ Al,
                                                 const __nv_bfloat16* __restrict__ Bh,
                                                 const __nv_bfloat16* __restrict__ Bl,
                                                 float* __restrict__ C,
                                                 int M, int N, int K) {
    extern __shared__ char sm[];
    uint32_t sb = smem_u32(sm);
    int t = threadIdx.x, wid = t >> 5, lane = t & 31;
    int bm = blockIdx.y * 128, bn = blockIdx.x * 128;
    int wm = wid >> 2, wn = wid & 3;          // warp tile origin (wm*64, wn*32)

    // global load geometry: thread t owns row t>>1, kgroup t&1 (8 bf16 = 16B)
    int srow = t >> 1, skg = t & 1;
    const char* pAh = (const char*)(Ah + (size_t)(bm + srow) * K + skg * 8);
    const char* pAl = (const char*)(Al + (size_t)(bm + srow) * K + skg * 8);
    const char* pBh = (const char*)(Bh + (size_t)(bn + srow) * K + skg * 8);
    const char* pBl = (const char*)(Bl + (size_t)(bn + srow) * K + skg * 8);
    uint32_t soff = uoff((uint32_t)t);        // store offset within region

    // ldmatrix address offsets
    int a_row = (lane & 7) + ((lane >> 3) & 1) * 8;
    int a_kg  = lane >> 4;
    int b_mat = lane >> 3;
    int b_n   = ((b_mat >> 1) & 1) * 8 + (lane & 7);
    int b_kg  = b_mat & 1;
    uint32_t aoff[4], boff[2];
#pragma unroll
    for (int mt = 0; mt < 4; mt++)
        aoff[mt] = uoff((uint32_t)((wm*64 + mt*16 + a_row) * 2 + a_kg));
#pragma unroll
    for (int np = 0; np < 2; np++)
        boff[np] = uoff((uint32_t)((wn*32 + np*16 + b_n) * 2 + b_kg));

    float acc[4][4][4];
#pragma unroll
    for (int i = 0; i < 4; i++)
#pragma unroll
        for (int j = 0; j < 4; j++)
#pragma unroll
            for (int q = 0; q < 4; q++) acc[i][j][q] = 0.f;

    int nk = K >> 4;
    int4 rAh = *(const int4*)pAh, rAl = *(const int4*)pAl;
    int4 rBh = *(const int4*)pBh, rBl = *(const int4*)pBl;
    {
        char* stg = sm;
        *(int4*)(stg +     0 + soff) = rAh;
        *(int4*)(stg +  4608 + soff) = rAl;
        *(int4*)(stg +  9216 + soff) = rBh;
        *(int4*)(stg + 13824 + soff) = rBl;
    }
    __syncthreads();

    for (int c = 0; c < nk; c++) {
        uint32_t stgb = sb + (c & 1) * GST;
        if (c + 1 < nk) {
            rAh = *(const int4*)(pAh + (c+1)*32);
            rAl = *(const int4*)(pAl + (c+1)*32);
            rBh = *(const int4*)(pBh + (c+1)*32);
            rBl = *(const int4*)(pBl + (c+1)*32);
        }
        uint32_t fah[4][4], fal[4][4], fbh[2][4], fbl[2][4];
#pragma unroll
        for (int mt = 0; mt < 4; mt++) {
            ldmx4(fah[mt], stgb +    0 + aoff[mt]);
            ldmx4(fal[mt], stgb + 4608 + aoff[mt]);
        }
#pragma unroll
        for (int np = 0; np < 2; np++) {
            ldmx4(fbh[np], stgb +  9216 + boff[np]);
            ldmx4(fbl[np], stgb + 13824 + boff[np]);
        }
#pragma unroll
        for (int mt = 0; mt < 4; mt++)
#pragma unroll
            for (int nt = 0; nt < 4; nt++) {
                int np = nt >> 1, sel = (nt & 1) * 2;
                mma16816(acc[mt][nt], fah[mt], fbh[np][sel], fbh[np][sel+1]);
                mma16816(acc[mt][nt], fah[mt], fbl[np][sel], fbl[np][sel+1]);
                mma16816(acc[mt][nt], fal[mt], fbh[np][sel], fbh[np][sel+1]);
            }
        __syncthreads();
        if (c + 1 < nk) {
            char* stg = sm + ((c+1) & 1) * GST;
            *(int4*)(stg +     0 + soff) = rAh;
            *(int4*)(stg +  4608 + soff) = rAl;
            *(int4*)(stg +  9216 + soff) = rBh;
            *(int4*)(stg + 13824 + soff) = rBl;
            __syncthreads();
        }
    }
    // epilogue
    int rr = lane >> 2, cc = (lane & 3) * 2;
#pragma unroll
    for (int mt = 0; mt < 4; mt++)
#pragma unroll
        for (int nt = 0; nt < 4; nt++) {
            size_t r0 = (size_t)(bm + wm*64 + mt*16 + rr) * N + bn + wn*32 + nt*8 + cc;
            *(float2*)&C[r0]         = make_float2(acc[mt][nt][0], acc[mt][nt][1]);
            *(float2*)&C[r0 + 8*N]   = make_float2(acc[mt][nt][2], acc[mt][nt][3]);
        }
}

// ---------------- layernorm of k over DK ----------------
__global__ __launch_bounds__(256) void ln_k_kernel() {
    int row  = blockIdx.x * 8 + (threadIdx.x >> 5);
    int lane = threadIdx.x & 31;
    int bl = row >> 4;
    int h  = row & 15;
    const float* kp = g_qkv + (size_t)bl * 3072 + 1024 + h * 64;
    float v0 = kp[lane], v1 = kp[lane + 32];
    float s = v0 + v1, ss = v0*v0 + v1*v1;
#pragma unroll
    for (int o = 16; o > 0; o >>= 1) {
        s  += __shfl_xor_sync(0xffffffffu, s,  o);
        ss += __shfl_xor_sync(0xffffffffu, ss, o);
    }
    float mu  = s * (1.f/64.f);
    float var = ss * (1.f/64.f) - mu*mu;
    float r   = rsqrtf(var + 1e-5f);
    float* o = g_kn + (size_t)bl * 1024 + h * 64;
    o[lane]      = (v0 - mu) * r;
    o[lane + 32] = (v1 - mu) * r;
}

// ---------------- causal flash attention (unchanged from R2) ----------------
#define ATTN_SMEM ((64*132 + 64*68 + 64*68 + 64*132 + 256)*4)
__global__ __launch_bounds__(256) void attn_kernel() {
    extern __shared__ float smf[];
    float* Qt = smf;
    float* Kt = Qt + 64*132;
    float* Vs = Kt + 64*68;
    float* Ps = Vs + 64*68;
    float* ms = Ps + 64*132;
    float* ls = ms + 128;

    int bh = blockIdx.x; int b = bh >> 4; int h = bh & 15;
    int q0 = (7 - blockIdx.y) * 128;
    int t  = threadIdx.x;
    int ty = t >> 4, tx = t & 15;
    int qi0 = ty * 8;
    int jj0 = tx * 4, dk0 = tx * 4;

    for (int i = t; i < 2048; i += 256) {
        int r = i >> 4, c = (i & 15) * 4;
        float4 qv = *(const float4*)&g_qkv[(size_t)(b*Lq + q0 + r) * 3072 + h*64 + c];
        Qt[(c+0)*132 + r] = qv.x; Qt[(c+1)*132 + r] = qv.y;
        Qt[(c+2)*132 + r] = qv.z; Qt[(c+3)*132 + r] = qv.w;
    }
    if (t < 128) { ms[t] = -1e30f; ls[t] = 0.f; }

    u64 acc2[4][4];
#pragma unroll
    for (int i = 0; i < 4; i++)
#pragma unroll
        for (int j = 0; j < 4; j++) acc2[i][j] = 0ull;
    __syncthreads();

    int ntiles = q0 / 64 + 2;
    for (int tile = 0; tile < ntiles; tile++) {
        int j0 = tile * 64;
        for (int i = t; i < 1024; i += 256) {
            int r = i >> 4, c = (i & 15) * 4;
            size_t base = (size_t)(b*Lq + j0 + r) * 3072 + h*64 + c;
            float4 kv = *(const float4*)&g_qkv[base + 1024];
            float4 vv = *(const float4*)&g_qkv[base + 2048];
            Kt[(c+0)*68 + r] = kv.x; Kt[(c+1)*68 + r] = kv.y;
            Kt[(c+2)*68 + r] = kv.z; Kt[(c+3)*68 + r] = kv.w;
            *(float4*)&Vs[r*68 + c] = vv;
        }
        __syncthreads();

        u64 s2[4][4];
#pragma unroll
        for (int i = 0; i < 4; i++)
#pragma unroll
            for (int j = 0; j < 4; j++) s2[i][j] = 0ull;
#pragma unroll 8
        for (int kk = 0; kk < 64; kk++) {
            const float* qrow = &Qt[kk*132 + qi0];
            u64 q2[4];
#pragma unroll
            for (int i2 = 0; i2 < 4; i2++) q2[i2] = *(const u64*)(qrow + 2*i2);
            float4 kv = *(const float4*)&Kt[kk*68 + jj0];
            u64 kd[4] = {dup2(kv.x), dup2(kv.y), dup2(kv.z), dup2(kv.w)};
#pragma unroll
            for (int i2 = 0; i2 < 4; i2++)
#pragma unroll
                for (int j = 0; j < 4; j++)
                    s2[i2][j] = fma2(q2[i2], kd[j], s2[i2][j]);
        }
        float sv[8][4];
#pragma unroll
        for (int i2 = 0; i2 < 4; i2++)
#pragma unroll
            for (int j = 0; j < 4; j++) {
                float lo, hi; upk2(s2[i2][j], lo, hi);
                sv[2*i2][j] = lo * 0.125f; sv[2*i2+1][j] = hi * 0.125f;
            }
        if (j0 >= q0) {
#pragma unroll
            for (int i = 0; i < 8; i++)
#pragma unroll
                for (int j = 0; j < 4; j++)
                    if (j0 + jj0 + j > q0 + qi0 + i) sv[i][j] = -1e30f;
        }
        float p[8][4], corr[8];
#pragma unroll
        for (int i = 0; i < 8; i++) {
            int r = qi0 + i;
            float mold = ms[r];
            float mx = fmaxf(fmaxf(sv[i][0], sv[i][1]), fmaxf(sv[i][2], sv[i][3]));
#pragma unroll
            for (int o = 1; o < 16; o <<= 1)
                mx = fmaxf(mx, __shfl_xor_sync(0xffffffffu, mx, o));
            float mt = fmaxf(mold, mx);
            float sum = 0.f;
#pragma unroll
            for (int j = 0; j < 4; j++) {
                float e = __expf(sv[i][j] - mt);
                p[i][j] = e; sum += e;
            }
#pragma unroll
            for (int o = 1; o < 16; o <<= 1)
                sum += __shfl_xor_sync(0xffffffffu, sum, o);
            corr[i] = __expf(mold - mt);
            if (tx == 0) { ms[r] = mt; ls[r] = ls[r] * corr[i] + sum; }
        }
#pragma unroll
        for (int j = 0; j < 4; j++) {
            *(float4*)&Ps[(jj0+j)*132 + qi0]     = make_float4(p[0][j], p[1][j], p[2][j], p[3][j]);
            *(float4*)&Ps[(jj0+j)*132 + qi0 + 4] = make_float4(p[4][j], p[5][j], p[6][j], p[7][j]);
        }
        __syncthreads();

        u64 corr2[4] = {pk2(corr[0], corr[1]), pk2(corr[2], corr[3]),
                        pk2(corr[4], corr[5]), pk2(corr[6], corr[7])};
#pragma unroll
        for (int i2 = 0; i2 < 4; i2++)
#pragma unroll
            for (int j = 0; j < 4; j++)
                acc2[i2][j] = mul2(acc2[i2][j], corr2[i2]);
#pragma unroll 8
        for (int jj = 0; jj < 64; jj++) {
            const float* prow = &Ps[jj*132 + qi0];
            u64 p2[4];
#pragma unroll
            for (int i2 = 0; i2 < 4; i2++) p2[i2] = *(const u64*)(prow + 2*i2);
            float4 vv = *(const float4*)&Vs[jj*68 + dk0];
            u64 vd[4] = {dup2(vv.x), dup2(vv.y), dup2(vv.z), dup2(vv.w)};
#pragma unroll
            for (int i2 = 0; i2 < 4; i2++)
#pragma unroll
                for (int j = 0; j < 4; j++)
                    acc2[i2][j] = fma2(p2[i2], vd[j], acc2[i2][j]);
        }
        __syncthreads();
    }
#pragma unroll
    for (int i2 = 0; i2 < 4; i2++) {
        float lo[4], hi[4];
#pragma unroll
        for (int j = 0; j < 4; j++) upk2(acc2[i2][j], lo[j], hi[j]);
        float l0 = 1.f / ls[qi0 + 2*i2], l1 = 1.f / ls[qi0 + 2*i2 + 1];
        size_t o0 = (size_t)(b*Lq + q0 + qi0 + 2*i2) * 1024 + h*64 + dk0;
        *(float4*)&g_so[o0]        = make_float4(lo[0]*l0, lo[1]*l0, lo[2]*l0, lo[3]*l0);
        *(float4*)&g_so[o0 + 1024] = make_float4(hi[0]*l1, hi[1]*l1, hi[2]*l1, hi[3]*l1);
    }
}

// ---------------- STP physics precompute ----------------
__global__ void stp_param_kernel(const float* __restrict__ W,   const float* __restrict__ Vgs,
                                 const float* __restrict__ VT0, const float* __restrict__ btau,
                                 const float* __restrict__ bgm, const float* __restrict__ Cch,
                                 const float* __restrict__ gam, const float* __restrict__ alpha,
                                 const float* __restrict__ ICt) {
    int idx = blockIdx.x * 256 + threadIdx.x;
    if (idx >= Hq*DKq*DKq) return;
    int h = idx >> 12;
    float veff = Vgs[h] - VT0[h] + W[idx];
    float sp   = (veff > 20.f) ? veff : log1pf(expf(veff));
    float gch  = btau[h] * sp;
    float invc = 1.f / Cch[h];
    float sig  = 1.f / (1.f + expf(-veff));
    float G    = bgm[h] * sp * sig;
    float smk  = tanhf(alpha[0] * (gch - ICt[0]));
    g_ret[idx]  = expf(-gch * invc);
    g_retC[idx] = expf(-gch * invc * (float)CHUNK);
    g_coef[idx] = gam[h] * smk * G;
}

// ---------------- STP pass A: chunk-local suffix sums (barrier-free loop) ----------------
#define PA_SMEM (2*CHUNK*64*4)
__global__ __launch_bounds__(256) void stp_passA() {
    extern __shared__ float sma[];
    float* sk = sma;
    float* sv = sma + CHUNK*64;
    int bid = blockIdx.x;
    int c  = bid & (NC - 1);
    int bh = bid >> 3;
    int h  = bh & 15, b = bh >> 4;
    int t  = threadIdx.x;
    int d  = t >> 2, e0 = (t & 3) * 16;
    int pbase = h*4096 + d*64 + e0;
    float rr[16], cf[16], Aa[16];
#pragma unroll
    for (int i = 0; i < 16; i++) { rr[i]=g_ret[pbase+i]; cf[i]=g_coef[pbase+i]; Aa[i]=0.f; }
    int t0 = c * CHUNK;
    size_t kb = (size_t)(b*Lq + t0) * 1024 + h*64;
    size_t vb = (size_t)(b*Lq + t0) * 3072 + 2048 + h*64;
    for (int idx = t; idx < 2048; idx += 256) {
        int s = idx >> 4, e4 = (idx & 15) * 4;
        *(float4*)&sk[s*64 + e4] = *(const float4*)&g_kn [kb + (size_t)s*1024 + e4];
        *(float4*)&sv[s*64 + e4] = *(const float4*)&g_qkv[vb + (size_t)s*3072 + e4];
    }
    __syncthreads();
#pragma unroll 2
    for (int s = 0; s < CHUNK; s++) {
        float vd = sv[s*64 + d];
        float4 k0 = *(const float4*)&sk[s*64 + e0];
        float4 k1 = *(const float4*)&sk[s*64 + e0 + 4];
        float4 k2 = *(const float4*)&sk[s*64 + e0 + 8];
        float4 k3 = *(const float4*)&sk[s*64 + e0 + 12];
        float kv[16] = {k0.x,k0.y,k0.z,k0.w, k1.x,k1.y,k1.z,k1.w,
                        k2.x,k2.y,k2.z,k2.w, k3.x,k3.y,k3.z,k3.w};
#pragma unroll
        for (int i = 0; i < 16; i++)
            Aa[i] = fmaf(rr[i], Aa[i], cf[i] * vd * kv[i]);
    }
    float* out = g_A + (size_t)bid * 4096 + d*64 + e0;
#pragma unroll
    for (int i = 0; i < 16; i++) out[i] = Aa[i];
}

// ---------------- STP pass B: inter-chunk scan ----------------
__global__ __launch_bounds__(256) void stp_passB() {
    int bh = blockIdx.x;
    int h  = bh & 15;
    int t  = threadIdx.x;
    int d = t >> 2, e0 = (t & 3) * 16;
    int pbase = h*4096 + d*64 + e0;
    float rc[16], F[16];
#pragma unroll
    for (int i = 0; i < 16; i++) { rc[i] = g_retC[pbase+i]; F[i] = 0.f; }
    size_t base = (size_t)bh * NC * 4096 + d*64 + e0;
    for (int c = 0; c < NC; c++) {
        float* fo = g_Fin + base + (size_t)c * 4096;
#pragma unroll
        for (int i = 0; i < 16; i++) fo[i] = F[i];
        if (c + 1 < NC) {
            const float* ai = g_A + base + (size_t)c * 4096;
#pragma unroll
            for (int i = 0; i < 16; i++) F[i] = fmaf(rc[i], F[i], ai[i]);
        }
    }
}

// ---------------- STP pass C: replay, emit y, gated mix, write bf16 split ymix ----------------
#define PC_SMEM (4*CHUNK*64*4)
__global__ __launch_bounds__(256) void stp_passC(const float* __restrict__ WL,
                                                 const float* __restrict__ gate) {
    extern __shared__ float smc[];
    float* sk = smc;
    float* sv = smc + CHUNK*64;
    float* sq = smc + 2*CHUNK*64;
    float* ys = smc + 3*CHUNK*64;
    int bid = blockIdx.x;
    int c  = bid & (NC - 1);
    int bh = bid >> 3;
    int h  = bh & 15, b = bh >> 4;
    int t  = threadIdx.x;
    int d  = t >> 2, e0 = (t & 3) * 16;
    int pbase = h*4096 + d*64 + e0;
    float rr[16], cf[16], Wm[16], F[16];
#pragma unroll
    for (int i = 0; i < 16; i++) {
        rr[i] = g_ret[pbase+i]; cf[i] = g_coef[pbase+i]; Wm[i] = WL[pbase+i];
    }
    const float* fin = g_Fin + (size_t)bid * 4096 + d*64 + e0;
#pragma unroll
    for (int i = 0; i < 16; i++) F[i] = fin[i];
    float gct = 1.f / (1.f + expf(-gate[h]));
    int t0 = c * CHUNK;
    size_t kb = (size_t)(b*Lq + t0) * 1024 + h*64;
    size_t qb = (size_t)(b*Lq + t0) * 3072 + h*64;
    for (int idx = t; idx < 2048; idx += 256) {
        int s = idx >> 4, e4 = (idx & 15) * 4;
        *(float4*)&sk[s*64 + e4] = *(const float4*)&g_kn [kb + (size_t)s*1024 + e4];
        *(float4*)&sv[s*64 + e4] = *(const float4*)&g_qkv[qb + (size_t)s*3072 + 2048 + e4];
        *(float4*)&sq[s*64 + e4] = *(const float4*)&g_qkv[qb + (size_t)s*3072 + e4];
    }
    __syncthreads();
    bool lead = (t & 3) == 0;
    for (int s = 0; s < CHUNK; s++) {
        float vd = sv[s*64 + d];
        float4 k0 = *(const float4*)&sk[s*64 + e0];
        float4 k1 = *(const float4*)&sk[s*64 + e0 + 4];
        float4 k2 = *(const float4*)&sk[s*64 + e0 + 8];
        float4 k3 = *(const float4*)&sk[s*64 + e0 + 12];
        float4 q0v = *(const float4*)&sq[s*64 + e0];
        float4 q1v = *(const float4*)&sq[s*64 + e0 + 4];
        float4 q2v = *(const float4*)&sq[s*64 + e0 + 8];
        float4 q3v = *(const float4*)&sq[s*64 + e0 + 12];
        float kv[16] = {k0.x,k0.y,k0.z,k0.w, k1.x,k1.y,k1.z,k1.w,
                        k2.x,k2.y,k2.z,k2.w, k3.x,k3.y,k3.z,k3.w};
        float qv[16] = {q0v.x,q0v.y,q0v.z,q0v.w, q1v.x,q1v.y,q1v.z,q1v.w,
                        q2v.x,q2v.y,q2v.z,q2v.w, q3v.x,q3v.y,q3v.z,q3v.w};
        float y = 0.f;
#pragma unroll
        for (int i = 0; i < 16; i++) {
            float Fi = fmaf(rr[i], F[i], cf[i] * vd * kv[i]);
            F[i] = Fi;
            y = fmaf(Wm[i] + Fi, qv[i], y);
        }
        y += __shfl_down_sync(0xffffffffu, y, 2);
        y += __shfl_down_sync(0xffffffffu, y, 1);
        if (lead) ys[s*64 + d] = y;
    }
    __syncthreads();
    for (int idx = t; idx < 8192; idx += 256) {
        int s = idx >> 6, dd = idx & 63;
        size_t a = kb + (size_t)s * 1024 + dd;
        float m = gct * g_so[a] + (1.f - gct) * ys[idx];
        __nv_bfloat16 hh = __float2bfloat16_rn(m);
        g_ymh[a] = hh;
        g_yml[a] = __float2bfloat16_rn(m - __bfloat162float(hh));
    }
}

// ---------------- launch ----------------
extern "C" void kernel_launch(void* const* d_in, const int* in_sizes, int n_in,
                              void* d_out, int out_size) {
    const float* x     = (const float*)d_in[0];
    const float* Wqkv  = (const float*)d_in[1];
    const float* Wo    = (const float*)d_in[2];
    const float* WLTM  = (const float*)d_in[3];
    const float* Vgs   = (const float*)d_in[4];
    const float* VT0   = (const float*)d_in[5];
    const float* btau  = (const float*)d_in[6];
    const float* bgm   = (const float*)d_in[7];
    const float* Cch   = (const float*)d_in[8];
    const float* gam   = (const float*)d_in[9];
    const float* alpha = (const float*)d_in[10];
    const float* ICt   = (const float*)d_in[11];
    const float* gate  = (const float*)d_in[12];
    float* out = (float*)d_out;

    float *qkvp;
    __nv_bfloat16 *xh, *xl, *ymh, *yml, *wqh, *wql, *woh, *wol;
    cudaGetSymbolAddress((void**)&qkvp, g_qkv);
    cudaGetSymbolAddress((void**)&xh,  g_xh);
    cudaGetSymbolAddress((void**)&xl,  g_xl);
    cudaGetSymbolAddress((void**)&ymh, g_ymh);
    cudaGetSymbolAddress((void**)&yml, g_yml);
    cudaGetSymbolAddress((void**)&wqh, g_wqh);
    cudaGetSymbolAddress((void**)&wql, g_wql);
    cudaGetSymbolAddress((void**)&woh, g_woh);
    cudaGetSymbolAddress((void**)&wol, g_wol);
    cudaFuncSetAttribute(attn_kernel, cudaFuncAttributeMaxDynamicSharedMemorySize, ATTN_SMEM);
    cudaFuncSetAttribute(gemm_bf16,   cudaFuncAttributeMaxDynamicSharedMemorySize, GEMM_SMEM);
    cudaFuncSetAttribute(stp_passA,   cudaFuncAttributeMaxDynamicSharedMemorySize, PA_SMEM);
    cudaFuncSetAttribute(stp_passC,   cudaFuncAttributeMaxDynamicSharedMemorySize, PC_SMEM);

    // 0) prep: split x; transpose+split weights
    split_plain<<<2048, 256>>>(x, xh, xl, Bq*Lq*Dq);
    transpose_split<<<dim3(96, 32), 256>>>(Wqkv, wqh, wql, 1024, 3072);
    transpose_split<<<dim3(32, 32), 256>>>(Wo,   woh, wol, 1024, 1024);
    // 1) qkv = x @ W_qkv   (bf16 split mma.sync, 3-product)
    gemm_bf16<<<dim3(24, 16), 256, GEMM_SMEM>>>(xh, xl, wqh, wql, qkvp, 2048, 3072, 1024);
    // 2) layernorm(k)
    ln_k_kernel<<<4096, 256>>>();
    // 3) STP coefficient precompute
    stp_param_kernel<<<(Hq*DKq*DKq + 255)/256, 256>>>(WLTM, Vgs, VT0, btau, bgm, Cch, gam, alpha, ICt);
    // 4) causal softmax attention
    attn_kernel<<<dim3(Bq*Hq, Lq/128), 256, ATTN_SMEM>>>();
    // 5-7) chunked linear-recurrence scan + gated mix (writes bf16-split ymix)
    stp_passA<<<Bq*Hq*NC, 256, PA_SMEM>>>();
    stp_passB<<<Bq*Hq, 256>>>();
    stp_passC<<<Bq*Hq*NC, 256, PC_SMEM>>>(WLTM, gate);
    // 8) out = ymix @ W_o  (bf16 split mma.sync)
    gemm_bf16<<<dim3(8, 16), 256, GEMM_SMEM>>>(ymh, yml, woh, wol, out, 2048, 1024, 1024);
}

// round 5
// speedup vs baseline: 2.4374x; 1.1756x over previous
#include <cuda_runtime.h>
#include <cuda_bf16.h>
#include <math.h>
#include <stdint.h>

#define Bq 2
#define Lq 1024
#define Dq 1024
#define Hq 16
#define DKq 64
#define CHUNK 128
#define NC (Lq/CHUNK)   /* 8 */

typedef unsigned long long u64;

// ---------------- helpers ----------------
__device__ __forceinline__ uint32_t smem_u32(const void* p) {
    uint32_t a;
    asm("{ .reg .u64 t; cvta.to.shared.u64 t, %1; cvt.u32.u64 %0, t; }" : "=r"(a) : "l"(p));
    return a;
}
__device__ __forceinline__ void ldmx4(uint32_t* r, uint32_t addr) {
    asm volatile("ldmatrix.sync.aligned.m8n8.x4.shared.b16 {%0,%1,%2,%3}, [%4];"
        : "=r"(r[0]), "=r"(r[1]), "=r"(r[2]), "=r"(r[3]) : "r"(addr));
}
__device__ __forceinline__ void mma16816(float* c, const uint32_t* a, uint32_t b0, uint32_t b1) {
    asm volatile("mma.sync.aligned.m16n8k16.row.col.f32.bf16.bf16.f32 "
        "{%0,%1,%2,%3}, {%4,%5,%6,%7}, {%8,%9}, {%0,%1,%2,%3};"
        : "+f"(c[0]), "+f"(c[1]), "+f"(c[2]), "+f"(c[3])
        : "r"(a[0]), "r"(a[1]), "r"(a[2]), "r"(a[3]), "r"(b0), "r"(b1));
}
__device__ __forceinline__ uint32_t cvt2bf(float lo, float hi) {
    uint32_t r;
    asm("cvt.rn.bf16x2.f32 %0, %1, %2;" : "=r"(r) : "f"(hi), "f"(lo));
    return r;
}
__device__ __forceinline__ float tobf_f(float v) {
    return __bfloat162float(__float2bfloat16_rn(v));
}
__device__ __forceinline__ void cpa16(uint32_t saddr, const void* g) {
    asm volatile("cp.async.ca.shared.global [%0], [%1], 16;" :: "r"(saddr), "l"(g));
}
#define CPA_COMMIT() asm volatile("cp.async.commit_group;" ::: "memory")
#define CPA_WAIT1()  asm volatile("cp.async.wait_group 1;" ::: "memory")

// ---------------- scratch ----------------
__device__ float g_qkv  [Bq*Lq*3*Dq];
__device__ float g_kn   [Bq*Lq*Dq];
__device__ float g_so   [Bq*Lq*Dq];
__device__ __nv_bfloat16 g_xh   [Bq*Lq*Dq];
__device__ __nv_bfloat16 g_xl   [Bq*Lq*Dq];
__device__ __nv_bfloat16 g_ymh  [Bq*Lq*Dq];
__device__ __nv_bfloat16 g_yml  [Bq*Lq*Dq];
__device__ __nv_bfloat16 g_wqh  [3*Dq*Dq];
__device__ __nv_bfloat16 g_wql  [3*Dq*Dq];
__device__ __nv_bfloat16 g_woh  [Dq*Dq];
__device__ __nv_bfloat16 g_wol  [Dq*Dq];
__device__ float g_ret  [Hq*DKq*DKq];
__device__ float g_coef [Hq*DKq*DKq];
__device__ float g_retC [Hq*DKq*DKq];
__device__ float g_A    [Bq*Hq*NC*DKq*DKq];
__device__ float g_Fin  [Bq*Hq*NC*DKq*DKq];

// ---------------- prep: plain bf16 hi/lo split ----------------
__global__ __launch_bounds__(256) void split_plain(const float* __restrict__ s,
                                                   __nv_bfloat16* __restrict__ dh,
                                                   __nv_bfloat16* __restrict__ dl, int n) {
    int i = blockIdx.x * 1024 + threadIdx.x * 4;
    if (i >= n) return;
    float4 v = *(const float4*)&s[i];
    float vs[4] = {v.x, v.y, v.z, v.w};
#pragma unroll
    for (int j = 0; j < 4; j++) {
        __nv_bfloat16 h = __float2bfloat16_rn(vs[j]);
        dh[i + j] = h;
        dl[i + j] = __float2bfloat16_rn(vs[j] - __bfloat162float(h));
    }
}

// ---------------- prep: transpose + split ----------------
__global__ __launch_bounds__(256) void transpose_split(const float* __restrict__ src,
                                                       __nv_bfloat16* __restrict__ dh,
                                                       __nv_bfloat16* __restrict__ dl,
                                                       int R, int C) {
    __shared__ float tile[32][33];
    int c0 = blockIdx.x * 32, r0 = blockIdx.y * 32;
    int tx = threadIdx.x & 31, ty = threadIdx.x >> 5;
#pragma unroll
    for (int i = 0; i < 4; i++)
        tile[ty + 8*i][tx] = src[(size_t)(r0 + ty + 8*i) * C + c0 + tx];
    __syncthreads();
#pragma unroll
    for (int i = 0; i < 4; i++) {
        float v = tile[tx][ty + 8*i];
        __nv_bfloat16 h = __float2bfloat16_rn(v);
        size_t o = (size_t)(c0 + ty + 8*i) * R + r0 + tx;
        dh[o] = h;
        dl[o] = __float2bfloat16_rn(v - __bfloat162float(h));
    }
}

// ---------------- bf16 split-GEMM, cp.async 3-stage: C = (Ah+Al) @ (Bh+Bl)^T ----------------
#define GST 18432
#define GEMM_SMEM (3*GST)
__device__ __forceinline__ uint32_t uoff(uint32_t u) { return u*16u + ((u >> 3) << 4); }

__global__ __launch_bounds__(256) void gemm_bf16(const __nv_bfloat16* __restrict__ Ah,
                                                 const __nv_bfloat16* __restrict__ Al,
                                                 const __nv_bfloat16* __restrict__ Bh,
                                                 const __nv_bfloat16* __restrict__ Bl,
                                                 float* __restrict__ C,
                                                 int M, int N, int K) {
    extern __shared__ char sm[];
    uint32_t sb = smem_u32(sm);
    int t = threadIdx.x, wid = t >> 5, lane = t & 31;
    int bm = blockIdx.y * 128, bn = blockIdx.x * 128;
    int wm = wid >> 2, wn = wid & 3;

    int srow = t >> 1, skg = t & 1;
    const char* pAh = (const char*)(Ah + (size_t)(bm + srow) * K + skg * 8);
    const char* pAl = (const char*)(Al + (size_t)(bm + srow) * K + skg * 8);
    const char* pBh = (const char*)(Bh + (size_t)(bn + srow) * K + skg * 8);
    const char* pBl = (const char*)(Bl + (size_t)(bn + srow) * K + skg * 8);
    uint32_t soff = uoff((uint32_t)t);

    int a_row = (lane & 7) + ((lane >> 3) & 1) * 8;
    int a_kg  = lane >> 4;
    int b_mat = lane >> 3;
    int b_n   = ((b_mat >> 1) & 1) * 8 + (lane & 7);
    int b_kg  = b_mat & 1;
    uint32_t aoff[4], boff[2];
#pragma unroll
    for (int mt = 0; mt < 4; mt++)
        aoff[mt] = uoff((uint32_t)((wm*64 + mt*16 + a_row) * 2 + a_kg));
#pragma unroll
    for (int np = 0; np < 2; np++)
        boff[np] = uoff((uint32_t)((wn*32 + np*16 + b_n) * 2 + b_kg));

    float acc[4][4][4];
#pragma unroll
    for (int i = 0; i < 4; i++)
#pragma unroll
        for (int j = 0; j < 4; j++)
#pragma unroll
            for (int q = 0; q < 4; q++) acc[i][j][q] = 0.f;

    int nk = K >> 4;
#define G_ISSUE(st) do { \
    uint32_t base = sb + ((st) % 3) * GST + soff; \
    cpa16(base +     0, pAh + (size_t)(st)*32); \
    cpa16(base +  4608, pAl + (size_t)(st)*32); \
    cpa16(base +  9216, pBh + (size_t)(st)*32); \
    cpa16(base + 13824, pBl + (size_t)(st)*32); \
} while (0)
    G_ISSUE(0); CPA_COMMIT();
    if (nk > 1) G_ISSUE(1);
    CPA_COMMIT();

    for (int c = 0; c < nk; c++) {
        CPA_WAIT1();
        __syncthreads();
        if (c + 2 < nk) G_ISSUE(c + 2);
        CPA_COMMIT();
        uint32_t stgb = sb + (c % 3) * GST;
        uint32_t fah[4][4], fal[4][4], fbh[2][4], fbl[2][4];
#pragma unroll
        for (int mt = 0; mt < 4; mt++) {
            ldmx4(fah[mt], stgb +    0 + aoff[mt]);
            ldmx4(fal[mt], stgb + 4608 + aoff[mt]);
        }
#pragma unroll
        for (int np = 0; np < 2; np++) {
            ldmx4(fbh[np], stgb +  9216 + boff[np]);
            ldmx4(fbl[np], stgb + 13824 + boff[np]);
        }
#pragma unroll
        for (int mt = 0; mt < 4; mt++)
#pragma unroll
            for (int nt = 0; nt < 4; nt++) {
                int np = nt >> 1, sel = (nt & 1) * 2;
                mma16816(acc[mt][nt], fah[mt], fbh[np][sel], fbh[np][sel+1]);
                mma16816(acc[mt][nt], fah[mt], fbl[np][sel], fbl[np][sel+1]);
                mma16816(acc[mt][nt], fal[mt], fbh[np][sel], fbh[np][sel+1]);
            }
        __syncthreads();
    }
#undef G_ISSUE
    int rr = lane >> 2, cc = (lane & 3) * 2;
#pragma unroll
    for (int mt = 0; mt < 4; mt++)
#pragma unroll
        for (int nt = 0; nt < 4; nt++) {
            size_t r0 = (size_t)(bm + wm*64 + mt*16 + rr) * N + bn + wn*32 + nt*8 + cc;
            *(float2*)&C[r0]       = make_float2(acc[mt][nt][0], acc[mt][nt][1]);
            *(float2*)&C[r0 + 8*N] = make_float2(acc[mt][nt][2], acc[mt][nt][3]);
        }
}

// ---------------- layernorm of k over DK ----------------
__global__ __launch_bounds__(256) void ln_k_kernel() {
    int row  = blockIdx.x * 8 + (threadIdx.x >> 5);
    int lane = threadIdx.x & 31;
    int bl = row >> 4;
    int h  = row & 15;
    const float* kp = g_qkv + (size_t)bl * 3072 + 1024 + h * 64;
    float v0 = kp[lane], v1 = kp[lane + 32];
    float s = v0 + v1, ss = v0*v0 + v1*v1;
#pragma unroll
    for (int o = 16; o > 0; o >>= 1) {
        s  += __shfl_xor_sync(0xffffffffu, s,  o);
        ss += __shfl_xor_sync(0xffffffffu, ss, o);
    }
    float mu  = s * (1.f/64.f);
    float var = ss * (1.f/64.f) - mu*mu;
    float r   = rsqrtf(var + 1e-5f);
    float* o = g_kn + (size_t)bl * 1024 + h * 64;
    o[lane]      = (v0 - mu) * r;
    o[lane + 32] = (v1 - mu) * r;
}

// ---------------- tensor-core causal flash attention ----------------
// QT=128 per CTA, KT=64 per tile, 8 warps x m16. Split-bf16 3-product for S and PV.
#define RS 72                    /* smem row stride (elems); 144B, ldmatrix conflict-free */
#define AQH 0
#define AQL 18432
#define AKH 36864
#define AKL 46080
#define AVH 55296
#define AVL 64512
#define AMS 73728
#define ALS 74240
#define ATTN_SMEM 74752
__global__ __launch_bounds__(256) void attn_mma() {
    extern __shared__ char smc[];
    uint32_t sb = smem_u32(smc);
    __nv_bfloat16* Qh  = (__nv_bfloat16*)(smc + AQH);
    __nv_bfloat16* Ql  = (__nv_bfloat16*)(smc + AQL);
    __nv_bfloat16* Kh  = (__nv_bfloat16*)(smc + AKH);
    __nv_bfloat16* Kl  = (__nv_bfloat16*)(smc + AKL);
    __nv_bfloat16* Vth = (__nv_bfloat16*)(smc + AVH);
    __nv_bfloat16* Vtl = (__nv_bfloat16*)(smc + AVL);
    float* ms = (float*)(smc + AMS);
    float* ls = (float*)(smc + ALS);

    int bh = blockIdx.x, b = bh >> 4, h = bh & 15;
    int q0 = (7 - blockIdx.y) * 128;          // heavy blocks first
    int t = threadIdx.x, wid = t >> 5, lane = t & 31;

    // load + split Q (row-major [qi][kk])
    for (int i = t; i < 2048; i += 256) {
        int r = i >> 4, c = (i & 15) * 4;
        float4 q = *(const float4*)&g_qkv[(size_t)(b*Lq + q0 + r) * 3072 + h*64 + c];
        float qa[4] = {q.x, q.y, q.z, q.w};
#pragma unroll
        for (int u = 0; u < 4; u++) {
            __nv_bfloat16 hi = __float2bfloat16_rn(qa[u]);
            Qh[r*RS + c + u] = hi;
            Ql[r*RS + c + u] = __float2bfloat16_rn(qa[u] - __bfloat162float(hi));
        }
    }
    if (t < 128) { ms[t] = -1e30f; ls[t] = 0.f; }

    // ldmatrix lane offsets
    int a_row = (lane & 7) + ((lane >> 3) & 1) * 8;
    int a_kg  = lane >> 4;
    int b_mat = lane >> 3;
    int b_n   = ((b_mat >> 1) & 1) * 8 + (lane & 7);
    int b_kg  = b_mat & 1;
    uint32_t qh_addr[4], ql_addr[4];
#pragma unroll
    for (int ks = 0; ks < 4; ks++) {
        uint32_t off = (uint32_t)((wid*16 + a_row) * RS + ks*16 + a_kg*8) * 2;
        qh_addr[ks] = sb + AQH + off;
        ql_addr[ks] = sb + AQL + off;
    }
    int rl = wid*16 + (lane >> 2), rh2 = rl + 8;

    float o[8][4];
#pragma unroll
    for (int nt = 0; nt < 8; nt++)
#pragma unroll
        for (int q = 0; q < 4; q++) o[nt][q] = 0.f;
    __syncthreads();

    int ntiles = q0 / 64 + 2;
    for (int tile = 0; tile < ntiles; tile++) {
        int j0 = tile * 64;
        // load + split K (row-major [jj][kk]) and V transposed ([dk][jj])
        for (int i = t; i < 1024; i += 256) {
            int r = i >> 4, c = (i & 15) * 4;
            size_t base = (size_t)(b*Lq + j0 + r) * 3072 + h*64 + c;
            float4 kv = *(const float4*)&g_qkv[base + 1024];
            float4 vv = *(const float4*)&g_qkv[base + 2048];
            float ka[4] = {kv.x, kv.y, kv.z, kv.w};
            float va[4] = {vv.x, vv.y, vv.z, vv.w};
#pragma unroll
            for (int u = 0; u < 4; u++) {
                __nv_bfloat16 khi = __float2bfloat16_rn(ka[u]);
                Kh[r*RS + c + u] = khi;
                Kl[r*RS + c + u] = __float2bfloat16_rn(ka[u] - __bfloat162float(khi));
                __nv_bfloat16 vhi = __float2bfloat16_rn(va[u]);
                Vth[(c+u)*RS + r] = vhi;
                Vtl[(c+u)*RS + r] = __float2bfloat16_rn(va[u] - __bfloat162float(vhi));
            }
        }
        __syncthreads();

        // ---- S = Q K^T : warp covers rows [wid*16, +16) x cols [0,64) ----
        float s[8][4];
#pragma unroll
        for (int nt = 0; nt < 8; nt++)
#pragma unroll
            for (int q = 0; q < 4; q++) s[nt][q] = 0.f;
#pragma unroll
        for (int ks = 0; ks < 4; ks++) {
            uint32_t ah[4], al[4];
            ldmx4(ah, qh_addr[ks]);
            ldmx4(al, ql_addr[ks]);
#pragma unroll
            for (int np = 0; np < 4; np++) {
                uint32_t ko = (uint32_t)((np*16 + b_n) * RS + ks*16 + b_kg*8) * 2;
                uint32_t bh4[4], bl4[4];
                ldmx4(bh4, sb + AKH + ko);
                ldmx4(bl4, sb + AKL + ko);
                mma16816(s[np*2],   ah, bh4[0], bh4[1]);
                mma16816(s[np*2+1], ah, bh4[2], bh4[3]);
                mma16816(s[np*2],   ah, bl4[0], bl4[1]);
                mma16816(s[np*2+1], ah, bl4[2], bl4[3]);
                mma16816(s[np*2],   al, bh4[0], bh4[1]);
                mma16816(s[np*2+1], al, bh4[2], bh4[3]);
            }
        }
        // scale + causal mask
#pragma unroll
        for (int nt = 0; nt < 8; nt++)
#pragma unroll
            for (int q = 0; q < 4; q++) s[nt][q] *= 0.125f;
        if (tile >= ntiles - 2) {
            int qlo = q0 + rl, qhi = q0 + rh2;
#pragma unroll
            for (int nt = 0; nt < 8; nt++) {
                int j = j0 + nt*8 + (lane & 3)*2;
                if (j     > qlo) s[nt][0] = -1e30f;
                if (j + 1 > qlo) s[nt][1] = -1e30f;
                if (j     > qhi) s[nt][2] = -1e30f;
                if (j + 1 > qhi) s[nt][3] = -1e30f;
            }
        }
        // ---- online softmax (quad reductions) ----
        float mlo = -1e30f, mhi = -1e30f;
#pragma unroll
        for (int nt = 0; nt < 8; nt++) {
            mlo = fmaxf(mlo, fmaxf(s[nt][0], s[nt][1]));
            mhi = fmaxf(mhi, fmaxf(s[nt][2], s[nt][3]));
        }
        mlo = fmaxf(mlo, __shfl_xor_sync(0xffffffffu, mlo, 1));
        mlo = fmaxf(mlo, __shfl_xor_sync(0xffffffffu, mlo, 2));
        mhi = fmaxf(mhi, __shfl_xor_sync(0xffffffffu, mhi, 1));
        mhi = fmaxf(mhi, __shfl_xor_sync(0xffffffffu, mhi, 2));
        float mol = ms[rl], moh = ms[rh2];
        float mtl = fmaxf(mol, mlo), mth = fmaxf(moh, mhi);
        float cl = __expf(mol - mtl), ch = __expf(moh - mth);
        float suml = 0.f, sumh = 0.f;
#pragma unroll
        for (int nt = 0; nt < 8; nt++) {
            s[nt][0] = __expf(s[nt][0] - mtl);
            s[nt][1] = __expf(s[nt][1] - mtl);
            s[nt][2] = __expf(s[nt][2] - mth);
            s[nt][3] = __expf(s[nt][3] - mth);
            suml += s[nt][0] + s[nt][1];
            sumh += s[nt][2] + s[nt][3];
        }
        suml += __shfl_xor_sync(0xffffffffu, suml, 1);
        suml += __shfl_xor_sync(0xffffffffu, suml, 2);
        sumh += __shfl_xor_sync(0xffffffffu, sumh, 1);
        sumh += __shfl_xor_sync(0xffffffffu, sumh, 2);
        if ((lane & 3) == 0) {
            ms[rl]  = mtl; ls[rl]  = ls[rl]  * cl + suml;
            ms[rh2] = mth; ls[rh2] = ls[rh2] * ch + sumh;
        }
        // rescale running PV accumulator
#pragma unroll
        for (int nt = 0; nt < 8; nt++) {
            o[nt][0] *= cl; o[nt][1] *= cl;
            o[nt][2] *= ch; o[nt][3] *= ch;
        }
        // ---- PV: P stays in registers (acc-frag == A-frag identity) ----
#pragma unroll
        for (int ks = 0; ks < 4; ks++) {
            float h00 = tobf_f(s[2*ks][0]),   h01 = tobf_f(s[2*ks][1]);
            float h02 = tobf_f(s[2*ks][2]),   h03 = tobf_f(s[2*ks][3]);
            float h10 = tobf_f(s[2*ks+1][0]), h11 = tobf_f(s[2*ks+1][1]);
            float h12 = tobf_f(s[2*ks+1][2]), h13 = tobf_f(s[2*ks+1][3]);
            uint32_t ph[4], pl[4];
            ph[0] = cvt2bf(h00, h01); ph[1] = cvt2bf(h02, h03);
            ph[2] = cvt2bf(h10, h11); ph[3] = cvt2bf(h12, h13);
            pl[0] = cvt2bf(s[2*ks][0]-h00,   s[2*ks][1]-h01);
            pl[1] = cvt2bf(s[2*ks][2]-h02,   s[2*ks][3]-h03);
            pl[2] = cvt2bf(s[2*ks+1][0]-h10, s[2*ks+1][1]-h11);
            pl[3] = cvt2bf(s[2*ks+1][2]-h12, s[2*ks+1][3]-h13);
#pragma unroll
            for (int np = 0; np < 4; np++) {
                uint32_t vo = (uint32_t)((np*16 + b_n) * RS + ks*16 + b_kg*8) * 2;
                uint32_t vh4[4], vl4[4];
                ldmx4(vh4, sb + AVH + vo);
                ldmx4(vl4, sb + AVL + vo);
                mma16816(o[np*2],   ph, vh4[0], vh4[1]);
                mma16816(o[np*2+1], ph, vh4[2], vh4[3]);
                mma16816(o[np*2],   ph, vl4[0], vl4[1]);
                mma16816(o[np*2+1], ph, vl4[2], vl4[3]);
                mma16816(o[np*2],   pl, vh4[0], vh4[1]);
                mma16816(o[np*2+1], pl, vh4[2], vh4[3]);
            }
        }
        __syncthreads();
    }
    // epilogue: normalize, store
    float li = 1.f / ls[rl], lh = 1.f / ls[rh2];
#pragma unroll
    for (int nt = 0; nt < 8; nt++) {
        size_t o0 = (size_t)(b*Lq + q0 + rl) * 1024 + h*64 + nt*8 + (lane & 3)*2;
        *(float2*)&g_so[o0]          = make_float2(o[nt][0]*li, o[nt][1]*li);
        *(float2*)&g_so[o0 + 8*1024] = make_float2(o[nt][2]*lh, o[nt][3]*lh);
    }
}

// ---------------- STP physics precompute ----------------
__global__ void stp_param_kernel(const float* __restrict__ W,   const float* __restrict__ Vgs,
                                 const float* __restrict__ VT0, const float* __restrict__ btau,
                                 const float* __restrict__ bgm, const float* __restrict__ Cch,
                                 const float* __restrict__ gam, const float* __restrict__ alpha,
                                 const float* __restrict__ ICt) {
    int idx = blockIdx.x * 256 + threadIdx.x;
    if (idx >= Hq*DKq*DKq) return;
    int h = idx >> 12;
    float veff = Vgs[h] - VT0[h] + W[idx];
    float sp   = (veff > 20.f) ? veff : log1pf(expf(veff));
    float gch  = btau[h] * sp;
    float invc = 1.f / Cch[h];
    float sig  = 1.f / (1.f + expf(-veff));
    float G    = bgm[h] * sp * sig;
    float smk  = tanhf(alpha[0] * (gch - ICt[0]));
    g_ret[idx]  = expf(-gch * invc);
    g_retC[idx] = expf(-gch * invc * (float)CHUNK);
    g_coef[idx] = gam[h] * smk * G;
}

// ---------------- STP pass A ----------------
#define PA_SMEM (2*CHUNK*64*4)
__global__ __launch_bounds__(256) void stp_passA() {
    extern __shared__ float sma[];
    float* sk = sma;
    float* sv = sma + CHUNK*64;
    int bid = blockIdx.x;
    int c  = bid & (NC - 1);
    int bh = bid >> 3;
    int h  = bh & 15, b = bh >> 4;
    int t  = threadIdx.x;
    int d  = t >> 2, e0 = (t & 3) * 16;
    int pbase = h*4096 + d*64 + e0;
    float rr[16], cf[16], Aa[16];
#pragma unroll
    for (int i = 0; i < 16; i++) { rr[i]=g_ret[pbase+i]; cf[i]=g_coef[pbase+i]; Aa[i]=0.f; }
    int t0 = c * CHUNK;
    size_t kb = (size_t)(b*Lq + t0) * 1024 + h*64;
    size_t vb = (size_t)(b*Lq + t0) * 3072 + 2048 + h*64;
    for (int idx = t; idx < 2048; idx += 256) {
        int s = idx >> 4, e4 = (idx & 15) * 4;
        *(float4*)&sk[s*64 + e4] = *(const float4*)&g_kn [kb + (size_t)s*1024 + e4];
        *(float4*)&sv[s*64 + e4] = *(const float4*)&g_qkv[vb + (size_t)s*3072 + e4];
    }
    __syncthreads();
#pragma unroll 2
    for (int s = 0; s < CHUNK; s++) {
        float vd = sv[s*64 + d];
        float4 k0 = *(const float4*)&sk[s*64 + e0];
        float4 k1 = *(const float4*)&sk[s*64 + e0 + 4];
        float4 k2 = *(const float4*)&sk[s*64 + e0 + 8];
        float4 k3 = *(const float4*)&sk[s*64 + e0 + 12];
        float kv[16] = {k0.x,k0.y,k0.z,k0.w, k1.x,k1.y,k1.z,k1.w,
                        k2.x,k2.y,k2.z,k2.w, k3.x,k3.y,k3.z,k3.w};
#pragma unroll
        for (int i = 0; i < 16; i++)
            Aa[i] = fmaf(rr[i], Aa[i], cf[i] * vd * kv[i]);
    }
    float* out = g_A + (size_t)bid * 4096 + d*64 + e0;
#pragma unroll
    for (int i = 0; i < 16; i++) out[i] = Aa[i];
}

// ---------------- STP pass B ----------------
__global__ __launch_bounds__(256) void stp_passB() {
    int bh = blockIdx.x;
    int h  = bh & 15;
    int t  = threadIdx.x;
    int d = t >> 2, e0 = (t & 3) * 16;
    int pbase = h*4096 + d*64 + e0;
    float rc[16], F[16];
#pragma unroll
    for (int i = 0; i < 16; i++) { rc[i] = g_retC[pbase+i]; F[i] = 0.f; }
    size_t base = (size_t)bh * NC * 4096 + d*64 + e0;
    for (int c = 0; c < NC; c++) {
        float* fo = g_Fin + base + (size_t)c * 4096;
#pragma unroll
        for (int i = 0; i < 16; i++) fo[i] = F[i];
        if (c + 1 < NC) {
            const float* ai = g_A + base + (size_t)c * 4096;
#pragma unroll
            for (int i = 0; i < 16; i++) F[i] = fmaf(rc[i], F[i], ai[i]);
        }
    }
}

// ---------------- STP pass C ----------------
#define PC_SMEM (4*CHUNK*64*4)
__global__ __launch_bounds__(256) void stp_passC(const float* __restrict__ WL,
                                                 const float* __restrict__ gate) {
    extern __shared__ float smcc[];
    float* sk = smcc;
    float* sv = smcc + CHUNK*64;
    float* sq = smcc + 2*CHUNK*64;
    float* ys = smcc + 3*CHUNK*64;
    int bid = blockIdx.x;
    int c  = bid & (NC - 1);
    int bh = bid >> 3;
    int h  = bh & 15, b = bh >> 4;
    int t  = threadIdx.x;
    int d  = t >> 2, e0 = (t & 3) * 16;
    int pbase = h*4096 + d*64 + e0;
    float rr[16], cf[16], Wm[16], F[16];
#pragma unroll
    for (int i = 0; i < 16; i++) {
        rr[i] = g_ret[pbase+i]; cf[i] = g_coef[pbase+i]; Wm[i] = WL[pbase+i];
    }
    const float* fin = g_Fin + (size_t)bid * 4096 + d*64 + e0;
#pragma unroll
    for (int i = 0; i < 16; i++) F[i] = fin[i];
    float gct = 1.f / (1.f + expf(-gate[h]));
    int t0 = c * CHUNK;
    size_t kb = (size_t)(b*Lq + t0) * 1024 + h*64;
    size_t qb = (size_t)(b*Lq + t0) * 3072 + h*64;
    for (int idx = t; idx < 2048; idx += 256) {
        int s = idx >> 4, e4 = (idx & 15) * 4;
        *(float4*)&sk[s*64 + e4] = *(const float4*)&g_kn [kb + (size_t)s*1024 + e4];
        *(float4*)&sv[s*64 + e4] = *(const float4*)&g_qkv[qb + (size_t)s*3072 + 2048 + e4];
        *(float4*)&sq[s*64 + e4] = *(const float4*)&g_qkv[qb + (size_t)s*3072 + e4];
    }
    __syncthreads();
    bool lead = (t & 3) == 0;
    for (int s = 0; s < CHUNK; s++) {
        float vd = sv[s*64 + d];
        float4 k0 = *(const float4*)&sk[s*64 + e0];
        float4 k1 = *(const float4*)&sk[s*64 + e0 + 4];
        float4 k2 = *(const float4*)&sk[s*64 + e0 + 8];
        float4 k3 = *(const float4*)&sk[s*64 + e0 + 12];
        float4 q0v = *(const float4*)&sq[s*64 + e0];
        float4 q1v = *(const float4*)&sq[s*64 + e0 + 4];
        float4 q2v = *(const float4*)&sq[s*64 + e0 + 8];
        float4 q3v = *(const float4*)&sq[s*64 + e0 + 12];
        float kv[16] = {k0.x,k0.y,k0.z,k0.w, k1.x,k1.y,k1.z,k1.w,
                        k2.x,k2.y,k2.z,k2.w, k3.x,k3.y,k3.z,k3.w};
        float qv[16] = {q0v.x,q0v.y,q0v.z,q0v.w, q1v.x,q1v.y,q1v.z,q1v.w,
                        q2v.x,q2v.y,q2v.z,q2v.w, q3v.x,q3v.y,q3v.z,q3v.w};
        float y = 0.f;
#pragma unroll
        for (int i = 0; i < 16; i++) {
            float Fi = fmaf(rr[i], F[i], cf[i] * vd * kv[i]);
            F[i] = Fi;
            y = fmaf(Wm[i] + Fi, qv[i], y);
        }
        y += __shfl_down_sync(0xffffffffu, y, 2);
        y += __shfl_down_sync(0xffffffffu, y, 1);
        if (lead) ys[s*64 + d] = y;
    }
    __syncthreads();
    for (int idx = t; idx < 8192; idx += 256) {
        int s = idx >> 6, dd = idx & 63;
        size_t a = kb + (size_t)s * 1024 + dd;
        float m = gct * g_so[a] + (1.f - gct) * ys[idx];
        __nv_bfloat16 hh = __float2bfloat16_rn(m);
        g_ymh[a] = hh;
        g_yml[a] = __float2bfloat16_rn(m - __bfloat162float(hh));
    }
}

// ---------------- launch ----------------
extern "C" void kernel_launch(void* const* d_in, const int* in_sizes, int n_in,
                              void* d_out, int out_size) {
    const float* x     = (const float*)d_in[0];
    const float* Wqkv  = (const float*)d_in[1];
    const float* Wo    = (const float*)d_in[2];
    const float* WLTM  = (const float*)d_in[3];
    const float* Vgs   = (const float*)d_in[4];
    const float* VT0   = (const float*)d_in[5];
    const float* btau  = (const float*)d_in[6];
    const float* bgm   = (const float*)d_in[7];
    const float* Cch   = (const float*)d_in[8];
    const float* gam   = (const float*)d_in[9];
    const float* alpha = (const float*)d_in[10];
    const float* ICt   = (const float*)d_in[11];
    const float* gate  = (const float*)d_in[12];
    float* out = (float*)d_out;

    float *qkvp;
    __nv_bfloat16 *xh, *xl, *ymh, *yml, *wqh, *wql, *woh, *wol;
    cudaGetSymbolAddress((void**)&qkvp, g_qkv);
    cudaGetSymbolAddress((void**)&xh,  g_xh);
    cudaGetSymbolAddress((void**)&xl,  g_xl);
    cudaGetSymbolAddress((void**)&ymh, g_ymh);
    cudaGetSymbolAddress((void**)&yml, g_yml);
    cudaGetSymbolAddress((void**)&wqh, g_wqh);
    cudaGetSymbolAddress((void**)&wql, g_wql);
    cudaGetSymbolAddress((void**)&woh, g_woh);
    cudaGetSymbolAddress((void**)&wol, g_wol);
    cudaFuncSetAttribute(attn_mma,  cudaFuncAttributeMaxDynamicSharedMemorySize, ATTN_SMEM);
    cudaFuncSetAttribute(gemm_bf16, cudaFuncAttributeMaxDynamicSharedMemorySize, GEMM_SMEM);
    cudaFuncSetAttribute(stp_passA, cudaFuncAttributeMaxDynamicSharedMemorySize, PA_SMEM);
    cudaFuncSetAttribute(stp_passC, cudaFuncAttributeMaxDynamicSharedMemorySize, PC_SMEM);

    split_plain<<<2048, 256>>>(x, xh, xl, Bq*Lq*Dq);
    transpose_split<<<dim3(96, 32), 256>>>(Wqkv, wqh, wql, 1024, 3072);
    transpose_split<<<dim3(32, 32), 256>>>(Wo,   woh, wol, 1024, 1024);
    gemm_bf16<<<dim3(24, 16), 256, GEMM_SMEM>>>(xh, xl, wqh, wql, qkvp, 2048, 3072, 1024);
    ln_k_kernel<<<4096, 256>>>();
    stp_param_kernel<<<(Hq*DKq*DKq + 255)/256, 256>>>(WLTM, Vgs, VT0, btau, bgm, Cch, gam, alpha, ICt);
    attn_mma<<<dim3(Bq*Hq, Lq/128), 256, ATTN_SMEM>>>();
    stp_passA<<<Bq*Hq*NC, 256, PA_SMEM>>>();
    stp_passB<<<Bq*Hq, 256>>>();
    stp_passC<<<Bq*Hq*NC, 256, PC_SMEM>>>(WLTM, gate);
    gemm_bf16<<<dim3(8, 16), 256, GEMM_SMEM>>>(ymh, yml, woh, wol, out, 2048, 1024, 1024);
}

// round 6
// speedup vs baseline: 2.6789x; 1.0991x over previous
#include <cuda_runtime.h>
#include <cuda_bf16.h>
#include <math.h>
#include <stdint.h>

#define Bq 2
#define Lq 1024
#define Dq 1024
#define Hq 16
#define DKq 64
#define CHUNK 128
#define NC (Lq/CHUNK)   /* 8 */

typedef unsigned long long u64;

// ---------------- helpers ----------------
__device__ __forceinline__ uint32_t smem_u32(const void* p) {
    uint32_t a;
    asm("{ .reg .u64 t; cvta.to.shared.u64 t, %1; cvt.u32.u64 %0, t; }" : "=r"(a) : "l"(p));
    return a;
}
__device__ __forceinline__ void ldmx4(uint32_t* r, uint32_t addr) {
    asm volatile("ldmatrix.sync.aligned.m8n8.x4.shared.b16 {%0,%1,%2,%3}, [%4];"
        : "=r"(r[0]), "=r"(r[1]), "=r"(r[2]), "=r"(r[3]) : "r"(addr));
}
__device__ __forceinline__ void mma16816(float* c, const uint32_t* a, uint32_t b0, uint32_t b1) {
    asm volatile("mma.sync.aligned.m16n8k16.row.col.f32.bf16.bf16.f32 "
        "{%0,%1,%2,%3}, {%4,%5,%6,%7}, {%8,%9}, {%0,%1,%2,%3};"
        : "+f"(c[0]), "+f"(c[1]), "+f"(c[2]), "+f"(c[3])
        : "r"(a[0]), "r"(a[1]), "r"(a[2]), "r"(a[3]), "r"(b0), "r"(b1));
}
__device__ __forceinline__ uint32_t cvt2bf(float lo, float hi) {
    uint32_t r;
    asm("cvt.rn.bf16x2.f32 %0, %1, %2;" : "=r"(r) : "f"(hi), "f"(lo));
    return r;
}
__device__ __forceinline__ float tobf_f(float v) {
    return __bfloat162float(__float2bfloat16_rn(v));
}
__device__ __forceinline__ void cpa16(uint32_t saddr, const void* g) {
    asm volatile("cp.async.ca.shared.global [%0], [%1], 16;" :: "r"(saddr), "l"(g));
}
#define CPA_COMMIT() asm volatile("cp.async.commit_group;" ::: "memory")
#define CPA_WAIT1()  asm volatile("cp.async.wait_group 1;" ::: "memory")
#define CPA_WAIT0()  asm volatile("cp.async.wait_group 0;" ::: "memory")

// pack 16 floats -> 8 bf16x2 hi + 8 bf16x2 lo
__device__ __forceinline__ void pack_split16(const float* f, uint32_t* rh, uint32_t* rl) {
#pragma unroll
    for (int j = 0; j < 8; j++) {
        float a = f[2*j], b = f[2*j+1];
        uint32_t p = cvt2bf(a, b);
        float ah = __uint_as_float(p << 16);
        float bh = __uint_as_float(p & 0xffff0000u);
        rh[j] = p;
        rl[j] = cvt2bf(a - ah, b - bh);
    }
}

// ---------------- scratch ----------------
__device__ float g_qkv  [Bq*Lq*3*Dq];
__device__ float g_kn   [Bq*Lq*Dq];
__device__ float g_so   [Bq*Lq*Dq];
__device__ __nv_bfloat16 g_xh   [Bq*Lq*Dq];
__device__ __nv_bfloat16 g_xl   [Bq*Lq*Dq];
__device__ __nv_bfloat16 g_ymh  [Bq*Lq*Dq];
__device__ __nv_bfloat16 g_yml  [Bq*Lq*Dq];
__device__ __nv_bfloat16 g_wqh  [3*Dq*Dq];
__device__ __nv_bfloat16 g_wql  [3*Dq*Dq];
__device__ __nv_bfloat16 g_woh  [Dq*Dq];
__device__ __nv_bfloat16 g_wol  [Dq*Dq];
// head-major split buffers for attention: [bh][l][dk] (q,k) and [bh][dk][l] (v transposed)
__device__ __nv_bfloat16 g_qh [Bq*Hq*Lq*DKq];
__device__ __nv_bfloat16 g_ql [Bq*Hq*Lq*DKq];
__device__ __nv_bfloat16 g_kh [Bq*Hq*Lq*DKq];
__device__ __nv_bfloat16 g_kl [Bq*Hq*Lq*DKq];
__device__ __nv_bfloat16 g_vth[Bq*Hq*DKq*Lq];
__device__ __nv_bfloat16 g_vtl[Bq*Hq*DKq*Lq];
__device__ float g_ret  [Hq*DKq*DKq];
__device__ float g_coef [Hq*DKq*DKq];
__device__ float g_retC [Hq*DKq*DKq];
__device__ float g_A    [Bq*Hq*NC*DKq*DKq];
__device__ float g_Fin  [Bq*Hq*NC*DKq*DKq];

// ---------------- prep: plain bf16 hi/lo split (for x) ----------------
__global__ __launch_bounds__(256) void split_plain(const float* __restrict__ s,
                                                   __nv_bfloat16* __restrict__ dh,
                                                   __nv_bfloat16* __restrict__ dl, int n) {
    int i = blockIdx.x * 1024 + threadIdx.x * 4;
    if (i >= n) return;
    float4 v = *(const float4*)&s[i];
    float vs[4] = {v.x, v.y, v.z, v.w};
#pragma unroll
    for (int j = 0; j < 4; j++) {
        __nv_bfloat16 h = __float2bfloat16_rn(vs[j]);
        dh[i + j] = h;
        dl[i + j] = __float2bfloat16_rn(vs[j] - __bfloat162float(h));
    }
}

// ---------------- prep: transpose + split (weights) ----------------
__global__ __launch_bounds__(256) void transpose_split(const float* __restrict__ src,
                                                       __nv_bfloat16* __restrict__ dh,
                                                       __nv_bfloat16* __restrict__ dl,
                                                       int R, int C) {
    __shared__ float tile[32][33];
    int c0 = blockIdx.x * 32, r0 = blockIdx.y * 32;
    int tx = threadIdx.x & 31, ty = threadIdx.x >> 5;
#pragma unroll
    for (int i = 0; i < 4; i++)
        tile[ty + 8*i][tx] = src[(size_t)(r0 + ty + 8*i) * C + c0 + tx];
    __syncthreads();
#pragma unroll
    for (int i = 0; i < 4; i++) {
        float v = tile[tx][ty + 8*i];
        __nv_bfloat16 h = __float2bfloat16_rn(v);
        size_t o = (size_t)(c0 + ty + 8*i) * R + r0 + tx;
        dh[o] = h;
        dl[o] = __float2bfloat16_rn(v - __bfloat162float(h));
    }
}

// ---------------- prep: split qkv to head-major bf16 (+ k layernorm) ----------------
// grid: (b*16+h)*16 + ltile ; 256 threads, 64 l-rows x 64 dk per block.
__global__ __launch_bounds__(256) void split_qkv() {
    __shared__ float vt[64][65];
    int bid = blockIdx.x;
    int lt = bid & 15;
    int bh = bid >> 4;
    int h = bh & 15, b = bh >> 4;
    int t = threadIdx.x;
    int lr = t >> 2, dk0 = (t & 3) * 16;
    int l = lt * 64 + lr;
    size_t base = (size_t)(b*Lq + l) * 3072 + h*64 + dk0;

    float q[16], k[16], v[16];
#pragma unroll
    for (int j = 0; j < 4; j++) {
        *(float4*)&q[4*j] = *(const float4*)&g_qkv[base + 4*j];
        *(float4*)&k[4*j] = *(const float4*)&g_qkv[base + 1024 + 4*j];
        *(float4*)&v[4*j] = *(const float4*)&g_qkv[base + 2048 + 4*j];
    }
    // layernorm(k) -> g_kn (quad = one l-row of 64)
    float s = 0.f, ss = 0.f;
#pragma unroll
    for (int j = 0; j < 16; j++) { s += k[j]; ss += k[j]*k[j]; }
    s  += __shfl_xor_sync(0xffffffffu, s, 1);  s  += __shfl_xor_sync(0xffffffffu, s, 2);
    ss += __shfl_xor_sync(0xffffffffu, ss, 1); ss += __shfl_xor_sync(0xffffffffu, ss, 2);
    float mu = s * (1.f/64.f);
    float var = ss * (1.f/64.f) - mu*mu;
    float rinv = rsqrtf(var + 1e-5f);
    size_t knb = (size_t)(b*Lq + l) * 1024 + h*64 + dk0;
#pragma unroll
    for (int j = 0; j < 4; j++) {
        float4 o = make_float4((k[4*j]-mu)*rinv, (k[4*j+1]-mu)*rinv,
                               (k[4*j+2]-mu)*rinv, (k[4*j+3]-mu)*rinv);
        *(float4*)&g_kn[knb + 4*j] = o;
    }
    // q,k splits -> [bh][l][dk]
    size_t ob = ((size_t)bh*Lq + l) * 64 + dk0;
    uint32_t rh[8], rl[8];
    pack_split16(q, rh, rl);
    *(uint4*)&g_qh[ob] = *(uint4*)&rh[0]; *(uint4*)&g_qh[ob+8] = *(uint4*)&rh[4];
    *(uint4*)&g_ql[ob] = *(uint4*)&rl[0]; *(uint4*)&g_ql[ob+8] = *(uint4*)&rl[4];
    pack_split16(k, rh, rl);
    *(uint4*)&g_kh[ob] = *(uint4*)&rh[0]; *(uint4*)&g_kh[ob+8] = *(uint4*)&rh[4];
    *(uint4*)&g_kl[ob] = *(uint4*)&rl[0]; *(uint4*)&g_kl[ob+8] = *(uint4*)&rl[4];
    // v transpose via smem -> [bh][dk][l]
#pragma unroll
    for (int j = 0; j < 16; j++) vt[dk0 + j][lr] = v[j];
    __syncthreads();
    int odk = t >> 2, l0 = (t & 3) * 16;
    float vv[16];
#pragma unroll
    for (int j = 0; j < 16; j++) vv[j] = vt[odk][l0 + j];
    pack_split16(vv, rh, rl);
    size_t vb = ((size_t)bh*64 + odk) * Lq + lt*64 + l0;
    *(uint4*)&g_vth[vb] = *(uint4*)&rh[0]; *(uint4*)&g_vth[vb+8] = *(uint4*)&rh[4];
    *(uint4*)&g_vtl[vb] = *(uint4*)&rl[0]; *(uint4*)&g_vtl[vb+8] = *(uint4*)&rl[4];
}

// ---------------- bf16 split-GEMM, k32 chunks, 3-stage cp.async ----------------
// region: 128 rows x 32 bf16, unit(16B) u = row*4 + kg, padded by 16B per 8 units.
#define GREG 9216
#define GST  36864
#define GEMM_SMEM (3*GST)
__device__ __forceinline__ uint32_t uoff(uint32_t u) { return u*16u + ((u >> 3) << 4); }

__global__ __launch_bounds__(256) void gemm_bf16(const __nv_bfloat16* __restrict__ Ah,
                                                 const __nv_bfloat16* __restrict__ Al,
                                                 const __nv_bfloat16* __restrict__ Bh,
                                                 const __nv_bfloat16* __restrict__ Bl,
                                                 float* __restrict__ C,
                                                 int M, int N, int K) {
    extern __shared__ char sm[];
    uint32_t sb = smem_u32(sm);
    int t = threadIdx.x, wid = t >> 5, lane = t & 31;
    int bm = blockIdx.y * 128, bn = blockIdx.x * 128;
    int wm = wid >> 2, wn = wid & 3;

    // global load geometry: thread owns units 2t, 2t+1 -> row=t>>1, kg = (t&1)*2, +1
    int srow = t >> 1;
    int kg0 = (t & 1) * 2;
    uint32_t so = uoff((uint32_t)(2*t));   // second unit at so+16
    const char* pAh = (const char*)Ah + ((size_t)(bm + srow) * K + kg0*8) * 2;
    const char* pAl = (const char*)Al + ((size_t)(bm + srow) * K + kg0*8) * 2;
    const char* pBh = (const char*)Bh + ((size_t)(bn + srow) * K + kg0*8) * 2;
    const char* pBl = (const char*)Bl + ((size_t)(bn + srow) * K + kg0*8) * 2;

    int a_row = (lane & 7) + ((lane >> 3) & 1) * 8;
    int a_kg  = lane >> 4;
    int b_mat = lane >> 3;
    int b_n   = ((b_mat >> 1) & 1) * 8 + (lane & 7);
    int b_kg  = b_mat & 1;
    uint32_t aoff[4][2], boff[2][2];
#pragma unroll
    for (int mt = 0; mt < 4; mt++)
#pragma unroll
        for (int g = 0; g < 2; g++)
            aoff[mt][g] = uoff((uint32_t)((wm*64 + mt*16 + a_row)*4 + g*2 + a_kg));
#pragma unroll
    for (int np = 0; np < 2; np++)
#pragma unroll
        for (int g = 0; g < 2; g++)
            boff[np][g] = uoff((uint32_t)((wn*32 + np*16 + b_n)*4 + g*2 + b_kg));

    float acc[4][4][4];
#pragma unroll
    for (int i = 0; i < 4; i++)
#pragma unroll
        for (int j = 0; j < 4; j++)
#pragma unroll
            for (int q = 0; q < 4; q++) acc[i][j][q] = 0.f;

    int nk = K >> 5;
#define G_ISSUE(st) do { \
    uint32_t bse = sb + ((st) % 3) * GST + so; \
    size_t gb = (size_t)(st) * 64; \
    cpa16(bse          , pAh + gb); cpa16(bse + 16         , pAh + gb + 16); \
    cpa16(bse + GREG   , pAl + gb); cpa16(bse + GREG + 16  , pAl + gb + 16); \
    cpa16(bse + 2*GREG , pBh + gb); cpa16(bse + 2*GREG + 16, pBh + gb + 16); \
    cpa16(bse + 3*GREG , pBl + gb); cpa16(bse + 3*GREG + 16, pBl + gb + 16); \
} while (0)
    G_ISSUE(0); CPA_COMMIT();
    if (nk > 1) G_ISSUE(1);
    CPA_COMMIT();

    for (int c = 0; c < nk; c++) {
        CPA_WAIT1();
        __syncthreads();
        if (c + 2 < nk) G_ISSUE(c + 2);
        CPA_COMMIT();
        uint32_t stgb = sb + (c % 3) * GST;
#pragma unroll
        for (int g = 0; g < 2; g++) {
            uint32_t fah[4][4], fal[4][4], fbh[2][4], fbl[2][4];
#pragma unroll
            for (int mt = 0; mt < 4; mt++) {
                ldmx4(fah[mt], stgb +        aoff[mt][g]);
                ldmx4(fal[mt], stgb + GREG + aoff[mt][g]);
            }
#pragma unroll
            for (int np = 0; np < 2; np++) {
                ldmx4(fbh[np], stgb + 2*GREG + boff[np][g]);
                ldmx4(fbl[np], stgb + 3*GREG + boff[np][g]);
            }
#pragma unroll
            for (int mt = 0; mt < 4; mt++)
#pragma unroll
                for (int nt = 0; nt < 4; nt++) {
                    int np = nt >> 1, sel = (nt & 1) * 2;
                    mma16816(acc[mt][nt], fah[mt], fbh[np][sel], fbh[np][sel+1]);
                    mma16816(acc[mt][nt], fah[mt], fbl[np][sel], fbl[np][sel+1]);
                    mma16816(acc[mt][nt], fal[mt], fbh[np][sel], fbh[np][sel+1]);
                }
        }
    }
#undef G_ISSUE
    __syncthreads();
    int rr = lane >> 2, cc = (lane & 3) * 2;
#pragma unroll
    for (int mt = 0; mt < 4; mt++)
#pragma unroll
        for (int nt = 0; nt < 4; nt++) {
            size_t r0 = (size_t)(bm + wm*64 + mt*16 + rr) * N + bn + wn*32 + nt*8 + cc;
            *(float2*)&C[r0]       = make_float2(acc[mt][nt][0], acc[mt][nt][1]);
            *(float2*)&C[r0 + 8*N] = make_float2(acc[mt][nt][2], acc[mt][nt][3]);
        }
}

// ---------------- tensor-core causal flash attention, cp.async feed ----------------
#define RS 72                 /* smem row stride elems = 144B */
#define AQH 0
#define AQL 18432
#define AKV 36864             /* KV stage base; stage = 4 x 9216 = 36864 */
#define AKVST 36864
#define AMS (AKV + 2*AKVST)
#define ALS (AMS + 512)
#define ATTN_SMEM (ALS + 512)
__global__ __launch_bounds__(256) void attn_mma() {
    extern __shared__ char smc[];
    uint32_t sb = smem_u32(smc);
    float* ms = (float*)(smc + AMS);
    float* ls = (float*)(smc + ALS);

    int bh = blockIdx.x, b = bh >> 4, h = bh & 15;
    int q0 = (7 - blockIdx.y) * 128;
    int t = threadIdx.x, wid = t >> 5, lane = t & 31;

    const char* Qhg = (const char*)(g_qh + (size_t)bh * Lq * 64);
    const char* Qlg = (const char*)(g_ql + (size_t)bh * Lq * 64);
    const char* Khg = (const char*)(g_kh + (size_t)bh * Lq * 64);
    const char* Klg = (const char*)(g_kl + (size_t)bh * Lq * 64);
    const char* Vhg = (const char*)(g_vth + (size_t)bh * 64 * Lq);
    const char* Vlg = (const char*)(g_vtl + (size_t)bh * 64 * Lq);

    // Q: 128 rows x 128B -> 1024 units x 2 regions; 4 per thread per region
#pragma unroll
    for (int i = 0; i < 4; i++) {
        int unit = t + 256*i;
        int row = unit >> 3, un = unit & 7;
        uint32_t sa = sb + row*144 + un*16;
        size_t gb = (size_t)(q0 + row)*128 + un*16;
        cpa16(sa + AQH, Qhg + gb);
        cpa16(sa + AQL, Qlg + gb);
    }
    // KV tile issue: 64 rows x 128B -> 512 units per region; 2 per thread per region
#define KV_ISSUE(tile) do { \
    uint32_t stg = sb + AKV + ((tile) & 1) * AKVST; \
    int j0i = (tile) * 64; \
    _Pragma("unroll") \
    for (int i2 = 0; i2 < 2; i2++) { \
        int unit = t + 256*i2; \
        int row = unit >> 3, un = unit & 7; \
        uint32_t sa = stg + row*144 + un*16; \
        size_t gk = (size_t)(j0i + row)*128 + un*16; \
        size_t gv = (size_t)row*2048 + (size_t)j0i*2 + un*16; \
        cpa16(sa         , Khg + gk); \
        cpa16(sa +  9216 , Klg + gk); \
        cpa16(sa + 18432 , Vhg + gv); \
        cpa16(sa + 27648 , Vlg + gv); \
    } \
} while (0)
    KV_ISSUE(0);
    CPA_COMMIT();
    if (t < 128) { ms[t] = -1e30f; ls[t] = 0.f; }

    int a_row = (lane & 7) + ((lane >> 3) & 1) * 8;
    int a_kg  = lane >> 4;
    int b_mat = lane >> 3;
    int b_n   = ((b_mat >> 1) & 1) * 8 + (lane & 7);
    int b_kg  = b_mat & 1;
    uint32_t qh_addr[4], ql_addr[4];
#pragma unroll
    for (int ks = 0; ks < 4; ks++) {
        uint32_t off = (uint32_t)((wid*16 + a_row) * RS + ks*16 + a_kg*8) * 2;
        qh_addr[ks] = sb + AQH + off;
        ql_addr[ks] = sb + AQL + off;
    }
    int rl = wid*16 + (lane >> 2), rh2 = rl + 8;

    float o[8][4];
#pragma unroll
    for (int nt = 0; nt < 8; nt++)
#pragma unroll
        for (int q = 0; q < 4; q++) o[nt][q] = 0.f;

    int ntiles = q0 / 64 + 2;
    for (int tile = 0; tile < ntiles; tile++) {
        int j0 = tile * 64;
        CPA_WAIT0();
        __syncthreads();
        if (tile + 1 < ntiles) KV_ISSUE(tile + 1);
        CPA_COMMIT();
        uint32_t stg = sb + AKV + (tile & 1) * AKVST;

        // ---- S = Q K^T ----
        float s[8][4];
#pragma unroll
        for (int nt = 0; nt < 8; nt++)
#pragma unroll
            for (int q = 0; q < 4; q++) s[nt][q] = 0.f;
#pragma unroll
        for (int ks = 0; ks < 4; ks++) {
            uint32_t ah[4], al[4];
            ldmx4(ah, qh_addr[ks]);
            ldmx4(al, ql_addr[ks]);
#pragma unroll
            for (int np = 0; np < 4; np++) {
                uint32_t ko = (uint32_t)((np*16 + b_n) * RS + ks*16 + b_kg*8) * 2;
                uint32_t bh4[4], bl4[4];
                ldmx4(bh4, stg + ko);
                ldmx4(bl4, stg + 9216 + ko);
                mma16816(s[np*2],   ah, bh4[0], bh4[1]);
                mma16816(s[np*2+1], ah, bh4[2], bh4[3]);
                mma16816(s[np*2],   ah, bl4[0], bl4[1]);
                mma16816(s[np*2+1], ah, bl4[2], bl4[3]);
                mma16816(s[np*2],   al, bh4[0], bh4[1]);
                mma16816(s[np*2+1], al, bh4[2], bh4[3]);
            }
        }
#pragma unroll
        for (int nt = 0; nt < 8; nt++)
#pragma unroll
            for (int q = 0; q < 4; q++) s[nt][q] *= 0.125f;
        if (tile >= ntiles - 2) {
            int qlo = q0 + rl, qhi = q0 + rh2;
#pragma unroll
            for (int nt = 0; nt < 8; nt++) {
                int j = j0 + nt*8 + (lane & 3)*2;
                if (j     > qlo) s[nt][0] = -1e30f;
                if (j + 1 > qlo) s[nt][1] = -1e30f;
                if (j     > qhi) s[nt][2] = -1e30f;
                if (j + 1 > qhi) s[nt][3] = -1e30f;
            }
        }
        // ---- online softmax ----
        float mlo = -1e30f, mhi = -1e30f;
#pragma unroll
        for (int nt = 0; nt < 8; nt++) {
            mlo = fmaxf(mlo, fmaxf(s[nt][0], s[nt][1]));
            mhi = fmaxf(mhi, fmaxf(s[nt][2], s[nt][3]));
        }
        mlo = fmaxf(mlo, __shfl_xor_sync(0xffffffffu, mlo, 1));
        mlo = fmaxf(mlo, __shfl_xor_sync(0xffffffffu, mlo, 2));
        mhi = fmaxf(mhi, __shfl_xor_sync(0xffffffffu, mhi, 1));
        mhi = fmaxf(mhi, __shfl_xor_sync(0xffffffffu, mhi, 2));
        float mol = ms[rl], moh = ms[rh2];
        float mtl = fmaxf(mol, mlo), mth = fmaxf(moh, mhi);
        float cl = __expf(mol - mtl), ch = __expf(moh - mth);
        float suml = 0.f, sumh = 0.f;
#pragma unroll
        for (int nt = 0; nt < 8; nt++) {
            s[nt][0] = __expf(s[nt][0] - mtl);
            s[nt][1] = __expf(s[nt][1] - mtl);
            s[nt][2] = __expf(s[nt][2] - mth);
            s[nt][3] = __expf(s[nt][3] - mth);
            suml += s[nt][0] + s[nt][1];
            sumh += s[nt][2] + s[nt][3];
        }
        suml += __shfl_xor_sync(0xffffffffu, suml, 1);
        suml += __shfl_xor_sync(0xffffffffu, suml, 2);
        sumh += __shfl_xor_sync(0xffffffffu, sumh, 1);
        sumh += __shfl_xor_sync(0xffffffffu, sumh, 2);
        if ((lane & 3) == 0) {
            ms[rl]  = mtl; ls[rl]  = ls[rl]  * cl + suml;
            ms[rh2] = mth; ls[rh2] = ls[rh2] * ch + sumh;
        }
#pragma unroll
        for (int nt = 0; nt < 8; nt++) {
            o[nt][0] *= cl; o[nt][1] *= cl;
            o[nt][2] *= ch; o[nt][3] *= ch;
        }
        // ---- PV ----
#pragma unroll
        for (int ks = 0; ks < 4; ks++) {
            float h00 = tobf_f(s[2*ks][0]),   h01 = tobf_f(s[2*ks][1]);
            float h02 = tobf_f(s[2*ks][2]),   h03 = tobf_f(s[2*ks][3]);
            float h10 = tobf_f(s[2*ks+1][0]), h11 = tobf_f(s[2*ks+1][1]);
            float h12 = tobf_f(s[2*ks+1][2]), h13 = tobf_f(s[2*ks+1][3]);
            uint32_t ph[4], pl[4];
            ph[0] = cvt2bf(h00, h01); ph[1] = cvt2bf(h02, h03);
            ph[2] = cvt2bf(h10, h11); ph[3] = cvt2bf(h12, h13);
            pl[0] = cvt2bf(s[2*ks][0]-h00,   s[2*ks][1]-h01);
            pl[1] = cvt2bf(s[2*ks][2]-h02,   s[2*ks][3]-h03);
            pl[2] = cvt2bf(s[2*ks+1][0]-h10, s[2*ks+1][1]-h11);
            pl[3] = cvt2bf(s[2*ks+1][2]-h12, s[2*ks+1][3]-h13);
#pragma unroll
            for (int np = 0; np < 4; np++) {
                uint32_t vo = (uint32_t)((np*16 + b_n) * RS + ks*16 + b_kg*8) * 2;
                uint32_t vh4[4], vl4[4];
                ldmx4(vh4, stg + 18432 + vo);
                ldmx4(vl4, stg + 27648 + vo);
                mma16816(o[np*2],   ph, vh4[0], vh4[1]);
                mma16816(o[np*2+1], ph, vh4[2], vh4[3]);
                mma16816(o[np*2],   ph, vl4[0], vl4[1]);
                mma16816(o[np*2+1], ph, vl4[2], vl4[3]);
                mma16816(o[np*2],   pl, vh4[0], vh4[1]);
                mma16816(o[np*2+1], pl, vh4[2], vh4[3]);
            }
        }
        __syncthreads();
    }
#undef KV_ISSUE
    float li = 1.f / ls[rl], lh = 1.f / ls[rh2];
#pragma unroll
    for (int nt = 0; nt < 8; nt++) {
        size_t o0 = (size_t)(b*Lq + q0 + rl) * 1024 + h*64 + nt*8 + (lane & 3)*2;
        *(float2*)&g_so[o0]          = make_float2(o[nt][0]*li, o[nt][1]*li);
        *(float2*)&g_so[o0 + 8*1024] = make_float2(o[nt][2]*lh, o[nt][3]*lh);
    }
}

// ---------------- STP physics precompute ----------------
__global__ void stp_param_kernel(const float* __restrict__ W,   const float* __restrict__ Vgs,
                                 const float* __restrict__ VT0, const float* __restrict__ btau,
                                 const float* __restrict__ bgm, const float* __restrict__ Cch,
                                 const float* __restrict__ gam, const float* __restrict__ alpha,
                                 const float* __restrict__ ICt) {
    int idx = blockIdx.x * 256 + threadIdx.x;
    if (idx >= Hq*DKq*DKq) return;
    int h = idx >> 12;
    float veff = Vgs[h] - VT0[h] + W[idx];
    float sp   = (veff > 20.f) ? veff : log1pf(expf(veff));
    float gch  = btau[h] * sp;
    float invc = 1.f / Cch[h];
    float sig  = 1.f / (1.f + expf(-veff));
    float G    = bgm[h] * sp * sig;
    float smk  = tanhf(alpha[0] * (gch - ICt[0]));
    g_ret[idx]  = expf(-gch * invc);
    g_retC[idx] = expf(-gch * invc * (float)CHUNK);
    g_coef[idx] = gam[h] * smk * G;
}

// ---------------- STP pass A ----------------
#define PA_SMEM (2*CHUNK*64*4)
__global__ __launch_bounds__(256) void stp_passA() {
    extern __shared__ float sma[];
    float* sk = sma;
    float* sv = sma + CHUNK*64;
    int bid = blockIdx.x;
    int c  = bid & (NC - 1);
    int bh = bid >> 3;
    int h  = bh & 15, b = bh >> 4;
    int t  = threadIdx.x;
    int d  = t >> 2, e0 = (t & 3) * 16;
    int pbase = h*4096 + d*64 + e0;
    float rr[16], cf[16], Aa[16];
#pragma unroll
    for (int i = 0; i < 16; i++) { rr[i]=g_ret[pbase+i]; cf[i]=g_coef[pbase+i]; Aa[i]=0.f; }
    int t0 = c * CHUNK;
    size_t kb = (size_t)(b*Lq + t0) * 1024 + h*64;
    size_t vb = (size_t)(b*Lq + t0) * 3072 + 2048 + h*64;
    for (int idx = t; idx < 2048; idx += 256) {
        int s = idx >> 4, e4 = (idx & 15) * 4;
        *(float4*)&sk[s*64 + e4] = *(const float4*)&g_kn [kb + (size_t)s*1024 + e4];
        *(float4*)&sv[s*64 + e4] = *(const float4*)&g_qkv[vb + (size_t)s*3072 + e4];
    }
    __syncthreads();
#pragma unroll 2
    for (int s = 0; s < CHUNK; s++) {
        float vd = sv[s*64 + d];
        float4 k0 = *(const float4*)&sk[s*64 + e0];
        float4 k1 = *(const float4*)&sk[s*64 + e0 + 4];
        float4 k2 = *(const float4*)&sk[s*64 + e0 + 8];
        float4 k3 = *(const float4*)&sk[s*64 + e0 + 12];
        float kv[16] = {k0.x,k0.y,k0.z,k0.w, k1.x,k1.y,k1.z,k1.w,
                        k2.x,k2.y,k2.z,k2.w, k3.x,k3.y,k3.z,k3.w};
#pragma unroll
        for (int i = 0; i < 16; i++)
            Aa[i] = fmaf(rr[i], Aa[i], cf[i] * vd * kv[i]);
    }
    float* out = g_A + (size_t)bid * 4096 + d*64 + e0;
#pragma unroll
    for (int i = 0; i < 16; i++) out[i] = Aa[i];
}

// ---------------- STP pass B ----------------
__global__ __launch_bounds__(256) void stp_passB() {
    int bh = blockIdx.x;
    int h  = bh & 15;
    int t  = threadIdx.x;
    int d = t >> 2, e0 = (t & 3) * 16;
    int pbase = h*4096 + d*64 + e0;
    float rc[16], F[16];
#pragma unroll
    for (int i = 0; i < 16; i++) { rc[i] = g_retC[pbase+i]; F[i] = 0.f; }
    size_t base = (size_t)bh * NC * 4096 + d*64 + e0;
    for (int c = 0; c < NC; c++) {
        float* fo = g_Fin + base + (size_t)c * 4096;
#pragma unroll
        for (int i = 0; i < 16; i++) fo[i] = F[i];
        if (c + 1 < NC) {
            const float* ai = g_A + base + (size_t)c * 4096;
#pragma unroll
            for (int i = 0; i < 16; i++) F[i] = fmaf(rc[i], F[i], ai[i]);
        }
    }
}

// ---------------- STP pass C ----------------
#define PC_SMEM (4*CHUNK*64*4)
__global__ __launch_bounds__(256) void stp_passC(const float* __restrict__ WL,
                                                 const float* __restrict__ gate) {
    extern __shared__ float smcc[];
    float* sk = smcc;
    float* sv = smcc + CHUNK*64;
    float* sq = smcc + 2*CHUNK*64;
    float* ys = smcc + 3*CHUNK*64;
    int bid = blockIdx.x;
    int c  = bid & (NC - 1);
    int bh = bid >> 3;
    int h  = bh & 15, b = bh >> 4;
    int t  = threadIdx.x;
    int d  = t >> 2, e0 = (t & 3) * 16;
    int pbase = h*4096 + d*64 + e0;
    float rr[16], cf[16], Wm[16], F[16];
#pragma unroll
    for (int i = 0; i < 16; i++) {
        rr[i] = g_ret[pbase+i]; cf[i] = g_coef[pbase+i]; Wm[i] = WL[pbase+i];
    }
    const float* fin = g_Fin + (size_t)bid * 4096 + d*64 + e0;
#pragma unroll
    for (int i = 0; i < 16; i++) F[i] = fin[i];
    float gct = 1.f / (1.f + expf(-gate[h]));
    int t0 = c * CHUNK;
    size_t kb = (size_t)(b*Lq + t0) * 1024 + h*64;
    size_t qb = (size_t)(b*Lq + t0) * 3072 + h*64;
    for (int idx = t; idx < 2048; idx += 256) {
        int s = idx >> 4, e4 = (idx & 15) * 4;
        *(float4*)&sk[s*64 + e4] = *(const float4*)&g_kn [kb + (size_t)s*1024 + e4];
        *(float4*)&sv[s*64 + e4] = *(const float4*)&g_qkv[qb + (size_t)s*3072 + 2048 + e4];
        *(float4*)&sq[s*64 + e4] = *(const float4*)&g_qkv[qb + (size_t)s*3072 + e4];
    }
    __syncthreads();
    bool lead = (t & 3) == 0;
    for (int s = 0; s < CHUNK; s++) {
        float vd = sv[s*64 + d];
        float4 k0 = *(const float4*)&sk[s*64 + e0];
        float4 k1 = *(const float4*)&sk[s*64 + e0 + 4];
        float4 k2 = *(const float4*)&sk[s*64 + e0 + 8];
        float4 k3 = *(const float4*)&sk[s*64 + e0 + 12];
        float4 q0v = *(const float4*)&sq[s*64 + e0];
        float4 q1v = *(const float4*)&sq[s*64 + e0 + 4];
        float4 q2v = *(const float4*)&sq[s*64 + e0 + 8];
        float4 q3v = *(const float4*)&sq[s*64 + e0 + 12];
        float kv[16] = {k0.x,k0.y,k0.z,k0.w, k1.x,k1.y,k1.z,k1.w,
                        k2.x,k2.y,k2.z,k2.w, k3.x,k3.y,k3.z,k3.w};
        float qv[16] = {q0v.x,q0v.y,q0v.z,q0v.w, q1v.x,q1v.y,q1v.z,q1v.w,
                        q2v.x,q2v.y,q2v.z,q2v.w, q3v.x,q3v.y,q3v.z,q3v.w};
        float y = 0.f;
#pragma unroll
        for (int i = 0; i < 16; i++) {
            float Fi = fmaf(rr[i], F[i], cf[i] * vd * kv[i]);
            F[i] = Fi;
            y = fmaf(Wm[i] + Fi, qv[i], y);
        }
        y += __shfl_down_sync(0xffffffffu, y, 2);
        y += __shfl_down_sync(0xffffffffu, y, 1);
        if (lead) ys[s*64 + d] = y;
    }
    __syncthreads();
    for (int idx = t; idx < 8192; idx += 256) {
        int s = idx >> 6, dd = idx & 63;
        size_t a = kb + (size_t)s * 1024 + dd;
        float m = gct * g_so[a] + (1.f - gct) * ys[idx];
        __nv_bfloat16 hh = __float2bfloat16_rn(m);
        g_ymh[a] = hh;
        g_yml[a] = __float2bfloat16_rn(m - __bfloat162float(hh));
    }
}

// ---------------- launch ----------------
extern "C" void kernel_launch(void* const* d_in, const int* in_sizes, int n_in,
                              void* d_out, int out_size) {
    const float* x     = (const float*)d_in[0];
    const float* Wqkv  = (const float*)d_in[1];
    const float* Wo    = (const float*)d_in[2];
    const float* WLTM  = (const float*)d_in[3];
    const float* Vgs   = (const float*)d_in[4];
    const float* VT0   = (const float*)d_in[5];
    const float* btau  = (const float*)d_in[6];
    const float* bgm   = (const float*)d_in[7];
    const float* Cch   = (const float*)d_in[8];
    const float* gam   = (const float*)d_in[9];
    const float* alpha = (const float*)d_in[10];
    const float* ICt   = (const float*)d_in[11];
    const float* gate  = (const float*)d_in[12];
    float* out = (float*)d_out;

    float *qkvp;
    __nv_bfloat16 *xh, *xl, *ymh, *yml, *wqh, *wql, *woh, *wol;
    cudaGetSymbolAddress((void**)&qkvp, g_qkv);
    cudaGetSymbolAddress((void**)&xh,  g_xh);
    cudaGetSymbolAddress((void**)&xl,  g_xl);
    cudaGetSymbolAddress((void**)&ymh, g_ymh);
    cudaGetSymbolAddress((void**)&yml, g_yml);
    cudaGetSymbolAddress((void**)&wqh, g_wqh);
    cudaGetSymbolAddress((void**)&wql, g_wql);
    cudaGetSymbolAddress((void**)&woh, g_woh);
    cudaGetSymbolAddress((void**)&wol, g_wol);
    cudaFuncSetAttribute(attn_mma,  cudaFuncAttributeMaxDynamicSharedMemorySize, ATTN_SMEM);
    cudaFuncSetAttribute(gemm_bf16, cudaFuncAttributeMaxDynamicSharedMemorySize, GEMM_SMEM);
    cudaFuncSetAttribute(stp_passA, cudaFuncAttributeMaxDynamicSharedMemorySize, PA_SMEM);
    cudaFuncSetAttribute(stp_passC, cudaFuncAttributeMaxDynamicSharedMemorySize, PC_SMEM);

    split_plain<<<2048, 256>>>(x, xh, xl, Bq*Lq*Dq);
    transpose_split<<<dim3(96, 32), 256>>>(Wqkv, wqh, wql, 1024, 3072);
    transpose_split<<<dim3(32, 32), 256>>>(Wo,   woh, wol, 1024, 1024);
    gemm_bf16<<<dim3(24, 16), 256, GEMM_SMEM>>>(xh, xl, wqh, wql, qkvp, 2048, 3072, 1024);
    split_qkv<<<512, 256>>>();
    stp_param_kernel<<<(Hq*DKq*DKq + 255)/256, 256>>>(WLTM, Vgs, VT0, btau, bgm, Cch, gam, alpha, ICt);
    attn_mma<<<dim3(Bq*Hq, Lq/128), 256, ATTN_SMEM>>>();
    stp_passA<<<Bq*Hq*NC, 256, PA_SMEM>>>();
    stp_passB<<<Bq*Hq, 256>>>();
    stp_passC<<<Bq*Hq*NC, 256, PC_SMEM>>>(WLTM, gate);
    gemm_bf16<<<dim3(8, 16), 256, GEMM_SMEM>>>(ymh, yml, woh, wol, out, 2048, 1024, 1024);
}